// round 2
// baseline (speedup 1.0000x reference)
#include <cuda_runtime.h>
#include <cuda_fp16.h>

#define BB  2
#define SS  2048
#define DD  1024
#define HH  1024
#define NHH 16
#define DHH 64

// ---------------------------------------------------------------------------
// Static device scratch.
//   g_Kn/g_Qn : natural-layout projections [B*S, H]           (16 MB each)
//   g_Vp      : head-split V projection [B, nh, S, dh]        (16 MB)
//   g_attn    : fp16 attention [B, nh, S(k=query), S(i=key)]  (256 MB)
//   g_X       : pre-output-projection activations [B,S,H]     (16 MB)
// ---------------------------------------------------------------------------
__device__ float g_Kn[BB * SS * HH];
__device__ float g_Qn[BB * SS * HH];
__device__ float g_Vp[BB * NHH * SS * DHH];
__device__ unsigned short g_attn[(size_t)BB * NHH * SS * SS];
__device__ float g_X[BB * SS * HH];

// ---------------------------------------------------------------------------
// Kernel 1: input projection  P = A @ W^T + b.
//   which 0/1 -> natural layout [B*S, H] (K, Q)
//   which 2   -> head-split [B, nh, S, dh] (V)
// ---------------------------------------------------------------------------
__global__ void __launch_bounds__(256) proj_kernel(const float* __restrict__ A,
                                                   const float* __restrict__ W,
                                                   const float* __restrict__ bias,
                                                   int which)
{
    float* out = (which == 0) ? g_Kn : (which == 1) ? g_Qn : g_Vp;

    __shared__ float As[16][132];
    __shared__ float Bs[16][132];

    const int bm = blockIdx.y * 128;
    const int bn = blockIdx.x * 128;
    const int tid = threadIdx.x;
    const int tx = tid & 15;
    const int ty = tid >> 4;

    float acc[8][8];
#pragma unroll
    for (int i = 0; i < 8; i++)
#pragma unroll
        for (int j = 0; j < 8; j++) acc[i][j] = 0.f;

    for (int k0 = 0; k0 < DD; k0 += 16) {
#pragma unroll
        for (int l = 0; l < 2; l++) {
            int f = tid + l * 256;
            int row = f >> 2;
            int c4 = (f & 3) << 2;
            float4 va = *(const float4*)(&A[(size_t)(bm + row) * DD + k0 + c4]);
            As[c4 + 0][row] = va.x; As[c4 + 1][row] = va.y;
            As[c4 + 2][row] = va.z; As[c4 + 3][row] = va.w;
            float4 vb = *(const float4*)(&W[(size_t)(bn + row) * DD + k0 + c4]);
            Bs[c4 + 0][row] = vb.x; Bs[c4 + 1][row] = vb.y;
            Bs[c4 + 2][row] = vb.z; Bs[c4 + 3][row] = vb.w;
        }
        __syncthreads();

#pragma unroll
        for (int kk = 0; kk < 16; kk++) {
            float a[8], b[8];
            *(float4*)&a[0] = *(float4*)&As[kk][ty * 8];
            *(float4*)&a[4] = *(float4*)&As[kk][ty * 8 + 4];
            *(float4*)&b[0] = *(float4*)&Bs[kk][tx * 8];
            *(float4*)&b[4] = *(float4*)&Bs[kk][tx * 8 + 4];
#pragma unroll
            for (int i = 0; i < 8; i++)
#pragma unroll
                for (int j = 0; j < 8; j++)
                    acc[i][j] += a[i] * b[j];
        }
        __syncthreads();
    }

    if (which == 2) {
#pragma unroll
        for (int j = 0; j < 8; j++) {
            int c = bn + tx * 8 + j;
            float bv = bias[c];
            int n = c & 15;
            int dcol = c >> 4;
#pragma unroll
            for (int i = 0; i < 8; i++) {
                int m = bm + ty * 8 + i;
                int b_ = m >> 11;
                int s = m & 2047;
                out[((size_t)(b_ * NHH + n) * SS + s) * DHH + dcol] = acc[i][j] + bv;
            }
        }
    } else {
#pragma unroll
        for (int j = 0; j < 8; j++) {
            int c = bn + tx * 8 + j;
            float bv = bias[c];
#pragma unroll
            for (int i = 0; i < 8; i++) {
                int m = bm + ty * 8 + i;
                out[(size_t)m * HH + c] = acc[i][j] + bv;
            }
        }
    }
}

// ---------------------------------------------------------------------------
// Kernel 2: fused score + head-softmax -> fp16 attn.
// Tile: 64 i (key rows) x 32 k (query rows) x all 16 heads. 512 threads.
// Warp w owns head h=w; lane r: i-frag r>>2 (8 wide), k-frag r&3 (8 wide).
// score[b,h,i,k] = sum_{c%16==h} Kn[b,i,c] * Qn[b,k,c]; softmax over h;
// store attn[b][h][k][i] fp16.
// ---------------------------------------------------------------------------
__global__ void __launch_bounds__(512, 1) score_softmax_kernel()
{
    __shared__ union {
        struct { float Ks[2][16][68]; float Qs[2][16][36]; } cl;
        float sm[16][4][72];
    } sh;

    const int bz = blockIdx.z;
    const int i_base = blockIdx.x * 64;
    const int k_base = blockIdx.y * 32;
    const float* Kb = g_Kn + ((size_t)bz * SS + i_base) * HH;
    const float* Qb = g_Qn + ((size_t)bz * SS + k_base) * HH;

    const int t = threadIdx.x;
    const int h = t >> 5;
    const int lane = t & 31;
    const int ig = lane >> 2;
    const int kg = lane & 3;

    const bool isK = (t < 256);
    const bool isQ = (t >= 256 && t < 384);
    const int lt = isK ? t : (t - 256);
    const int lrow = lt >> 2;
    const int lcq = (lt & 3) << 2;
    const float* lptr = isK ? (Kb + (size_t)lrow * HH + lcq)
                            : (Qb + (size_t)lrow * HH + lcq);

    float acc[8][8];
#pragma unroll
    for (int i = 0; i < 8; i++)
#pragma unroll
        for (int j = 0; j < 8; j++) acc[i][j] = 0.f;

    // prefetch chunk 0
    float4 pref = make_float4(0.f, 0.f, 0.f, 0.f);
    if (isK || isQ) pref = *(const float4*)lptr;
    if (isK) {
        sh.cl.Ks[0][lcq + 0][lrow] = pref.x;
        sh.cl.Ks[0][lcq + 1][lrow] = pref.y;
        sh.cl.Ks[0][lcq + 2][lrow] = pref.z;
        sh.cl.Ks[0][lcq + 3][lrow] = pref.w;
    } else if (isQ) {
        sh.cl.Qs[0][lcq + 0][lrow] = pref.x;
        sh.cl.Qs[0][lcq + 1][lrow] = pref.y;
        sh.cl.Qs[0][lcq + 2][lrow] = pref.z;
        sh.cl.Qs[0][lcq + 3][lrow] = pref.w;
    }
    __syncthreads();

    for (int ch = 0; ch < 64; ch++) {
        const int cb = ch & 1;
        if (ch < 63 && (isK || isQ))
            pref = *(const float4*)(lptr + (size_t)(ch + 1) * 16);

        float a[8], bq[8];
        const float* kr = &sh.cl.Ks[cb][h][ig * 8];
        *(float4*)&a[0] = *(const float4*)kr;
        *(float4*)&a[4] = *(const float4*)(kr + 4);
        const float* qr = &sh.cl.Qs[cb][h][kg * 8];
        *(float4*)&bq[0] = *(const float4*)qr;
        *(float4*)&bq[4] = *(const float4*)(qr + 4);
#pragma unroll
        for (int ii = 0; ii < 8; ii++)
#pragma unroll
            for (int kk = 0; kk < 8; kk++)
                acc[ii][kk] += a[ii] * bq[kk];

        if (ch < 63) {
            const int nb = cb ^ 1;
            if (isK) {
                sh.cl.Ks[nb][lcq + 0][lrow] = pref.x;
                sh.cl.Ks[nb][lcq + 1][lrow] = pref.y;
                sh.cl.Ks[nb][lcq + 2][lrow] = pref.z;
                sh.cl.Ks[nb][lcq + 3][lrow] = pref.w;
            } else if (isQ) {
                sh.cl.Qs[nb][lcq + 0][lrow] = pref.x;
                sh.cl.Qs[nb][lcq + 1][lrow] = pref.y;
                sh.cl.Qs[nb][lcq + 2][lrow] = pref.z;
                sh.cl.Qs[nb][lcq + 3][lrow] = pref.w;
            }
        }
        __syncthreads();
    }

    // ---- head-axis softmax, 8 rounds over the k-inner index ----
    const int b16 = bz * NHH;
#pragma unroll
    for (int rr = 0; rr < 8; rr++) {
#pragma unroll
        for (int ii = 0; ii < 8; ii++)
            sh.sm[h][kg][ig * 8 + ii] = acc[ii][rr] * 0.125f;
        __syncthreads();
        if (t < 256) {
            const int i_loc = t & 63;
            const int kq = t >> 6;
            float v[16];
            float mx = -1e30f;
#pragma unroll
            for (int hh = 0; hh < 16; hh++) {
                v[hh] = sh.sm[hh][kq][i_loc];
                mx = fmaxf(mx, v[hh]);
            }
            float sum = 0.f;
#pragma unroll
            for (int hh = 0; hh < 16; hh++) {
                v[hh] = __expf(v[hh] - mx);
                sum += v[hh];
            }
            const float inv = 1.f / sum;
            const size_t kgl = (size_t)(k_base + kq * 8 + rr);
            const size_t igl = (size_t)(i_base + i_loc);
#pragma unroll
            for (int hh = 0; hh < 16; hh++) {
                size_t idx = ((size_t)(b16 + hh) * SS + kgl) * SS + igl;
                g_attn[idx] = __half_as_ushort(__float2half_rn(v[hh] * inv));
            }
        }
        __syncthreads();
    }
}

// ---------------------------------------------------------------------------
// Kernel 3: AV. Per (b,h): X[b, k, j*16+h] = sum_i attn[b,h,k,i] * Vp[b,h,i,j]
// A: fp16 [k][i] row-major (i contiguous). M=128 k x N=64 j per CTA,
// 128 threads, 8x8 per thread, i-chunks of 16.
// ---------------------------------------------------------------------------
__global__ void __launch_bounds__(128) av2_kernel()
{
    const int bh = blockIdx.y;
    const int b_ = bh >> 4;
    const int hn = bh & 15;
    const __half* A = (const __half*)g_attn + (size_t)bh * SS * SS;
    const float* V = g_Vp + (size_t)bh * SS * DHH;
    const int k_base = blockIdx.x * 128;

    __shared__ float As[16][136];
    __shared__ float Vs[16][68];

    const int t = threadIdx.x;
    const int kgrp = t >> 3;
    const int jgrp = t & 7;

    float acc[8][8];
#pragma unroll
    for (int i = 0; i < 8; i++)
#pragma unroll
        for (int j = 0; j < 8; j++) acc[i][j] = 0.f;

    const __half* arow = A + (size_t)(k_base + t) * SS;
    const int vf = t * 2;
    const int vr0 = vf >> 4, vc0 = (vf & 15) << 2;
    const int vr1 = (vf + 1) >> 4, vc1 = ((vf + 1) & 15) << 2;

    uint4 pa0 = ((const uint4*)arow)[0];
    uint4 pa1 = ((const uint4*)arow)[1];
    float4 pv0 = *(const float4*)&V[(size_t)vr0 * DHH + vc0];
    float4 pv1 = *(const float4*)&V[(size_t)vr1 * DHH + vc1];

    for (int i0 = 0; i0 < SS; i0 += 16) {
        // stage prefetched chunk into smem
        {
            const __half2* h2 = (const __half2*)&pa0;
#pragma unroll
            for (int w = 0; w < 4; w++) {
                float2 f = __half22float2(h2[w]);
                As[w * 2][t] = f.x;
                As[w * 2 + 1][t] = f.y;
            }
            const __half2* h3 = (const __half2*)&pa1;
#pragma unroll
            for (int w = 0; w < 4; w++) {
                float2 f = __half22float2(h3[w]);
                As[8 + w * 2][t] = f.x;
                As[8 + w * 2 + 1][t] = f.y;
            }
            *(float4*)&Vs[vr0][vc0] = pv0;
            *(float4*)&Vs[vr1][vc1] = pv1;
        }
        __syncthreads();

        if (i0 + 16 < SS) {
            pa0 = ((const uint4*)(arow + i0 + 16))[0];
            pa1 = ((const uint4*)(arow + i0 + 16))[1];
            pv0 = *(const float4*)&V[(size_t)(i0 + 16 + vr0) * DHH + vc0];
            pv1 = *(const float4*)&V[(size_t)(i0 + 16 + vr1) * DHH + vc1];
        }

#pragma unroll
        for (int i = 0; i < 16; i++) {
            float a[8], b[8];
            *(float4*)&a[0] = *(const float4*)&As[i][kgrp * 8];
            *(float4*)&a[4] = *(const float4*)&As[i][kgrp * 8 + 4];
            *(float4*)&b[0] = *(const float4*)&Vs[i][jgrp * 8];
            *(float4*)&b[4] = *(const float4*)&Vs[i][jgrp * 8 + 4];
#pragma unroll
            for (int kk = 0; kk < 8; kk++)
#pragma unroll
                for (int jj = 0; jj < 8; jj++)
                    acc[kk][jj] += a[kk] * b[jj];
        }
        __syncthreads();
    }

#pragma unroll
    for (int kk = 0; kk < 8; kk++) {
        int kq = k_base + kgrp * 8 + kk;
        float* xr = g_X + ((size_t)b_ * SS + kq) * HH + hn;
#pragma unroll
        for (int jj = 0; jj < 8; jj++)
            xr[(jgrp * 8 + jj) * 16] = acc[kk][jj];
    }
}

// ---------------------------------------------------------------------------
// Kernel 4: output projection  res = X @ Wo^T + Wo_b
// ---------------------------------------------------------------------------
__global__ void __launch_bounds__(256) outproj_kernel(const float* __restrict__ Wo,
                                                      const float* __restrict__ bias,
                                                      float* __restrict__ out)
{
    const float* A = g_X;

    __shared__ float As[16][132];
    __shared__ float Bs[16][132];

    const int bm = blockIdx.y * 128;
    const int bn = blockIdx.x * 128;
    const int tid = threadIdx.x;
    const int tx = tid & 15;
    const int ty = tid >> 4;

    float acc[8][8];
#pragma unroll
    for (int i = 0; i < 8; i++)
#pragma unroll
        for (int j = 0; j < 8; j++) acc[i][j] = 0.f;

    for (int k0 = 0; k0 < HH; k0 += 16) {
#pragma unroll
        for (int l = 0; l < 2; l++) {
            int f = tid + l * 256;
            int row = f >> 2;
            int c4 = (f & 3) << 2;
            float4 va = *(const float4*)(&A[(size_t)(bm + row) * HH + k0 + c4]);
            As[c4 + 0][row] = va.x; As[c4 + 1][row] = va.y;
            As[c4 + 2][row] = va.z; As[c4 + 3][row] = va.w;
            float4 vb = *(const float4*)(&Wo[(size_t)(bn + row) * HH + k0 + c4]);
            Bs[c4 + 0][row] = vb.x; Bs[c4 + 1][row] = vb.y;
            Bs[c4 + 2][row] = vb.z; Bs[c4 + 3][row] = vb.w;
        }
        __syncthreads();

#pragma unroll
        for (int kk = 0; kk < 16; kk++) {
            float a[8], b[8];
            *(float4*)&a[0] = *(float4*)&As[kk][ty * 8];
            *(float4*)&a[4] = *(float4*)&As[kk][ty * 8 + 4];
            *(float4*)&b[0] = *(float4*)&Bs[kk][tx * 8];
            *(float4*)&b[4] = *(float4*)&Bs[kk][tx * 8 + 4];
#pragma unroll
            for (int i = 0; i < 8; i++)
#pragma unroll
                for (int j = 0; j < 8; j++)
                    acc[i][j] += a[i] * b[j];
        }
        __syncthreads();
    }

#pragma unroll
    for (int j = 0; j < 8; j++) {
        int c = bn + tx * 8 + j;
        float bv = bias[c];
#pragma unroll
        for (int i = 0; i < 8; i++) {
            int m = bm + ty * 8 + i;
            out[(size_t)m * HH + c] = acc[i][j] + bv;
        }
    }
}

// ---------------------------------------------------------------------------
// Launch
// ---------------------------------------------------------------------------
extern "C" void kernel_launch(void* const* d_in, const int* in_sizes, int n_in,
                              void* d_out, int out_size)
{
    const float* KEY   = (const float*)d_in[0];
    const float* VALUE = (const float*)d_in[1];
    const float* QUERY = (const float*)d_in[2];
    const float* Wk_w  = (const float*)d_in[3];
    const float* Wk_b  = (const float*)d_in[4];
    const float* Wq_w  = (const float*)d_in[5];
    const float* Wq_b  = (const float*)d_in[6];
    const float* Wv_w  = (const float*)d_in[7];
    const float* Wv_b  = (const float*)d_in[8];
    const float* Wo_w  = (const float*)d_in[9];
    const float* Wo_b  = (const float*)d_in[10];
    float* out = (float*)d_out;

    dim3 pg(HH / 128, (BB * SS) / 128);          // (8, 32)
    proj_kernel<<<pg, 256>>>(KEY,   Wk_w, Wk_b, 0);
    proj_kernel<<<pg, 256>>>(QUERY, Wq_w, Wq_b, 1);
    proj_kernel<<<pg, 256>>>(VALUE, Wv_w, Wv_b, 2);

    dim3 sg(SS / 64, SS / 32, BB);               // (32, 64, 2)
    score_softmax_kernel<<<sg, 512>>>();

    dim3 ag(SS / 128, BB * NHH);                 // (16, 32)
    av2_kernel<<<ag, 128>>>();

    dim3 og(HH / 128, (BB * SS) / 128);          // (8, 32)
    outproj_kernel<<<og, 256>>>(Wo_w, Wo_b, out);
}

// round 3
// speedup vs baseline: 4.1060x; 4.1060x over previous
#include <cuda_runtime.h>
#include <cuda_fp16.h>

#define BB  2
#define SS  2048
#define DD  1024
#define HH  1024
#define NHH 16
#define DHH 64

// ---------------------------------------------------------------------------
// Static scratch
// ---------------------------------------------------------------------------
__device__ __half g_A16[3][BB * SS * DD];          // fp16 KEY, QUERY, VALUE
__device__ __half g_W16[4][HH * DD];               // fp16 Wk, Wq, Wv, Wo
__device__ __half g_Kh[BB * NHH * SS * DHH];       // head-split projections
__device__ __half g_Qh[BB * NHH * SS * DHH];
__device__ __half g_Vh[BB * NHH * SS * DHH];
__device__ __half g_attn[(size_t)BB * NHH * SS * SS];   // attn [b,h,k,i]
__device__ __half g_Xt[BB * HH * SS];              // X transposed [b][c][s]

// ---------------------------------------------------------------------------
// PTX helpers
// ---------------------------------------------------------------------------
__device__ __forceinline__ unsigned sptr(const void* p) {
    unsigned a;
    asm("{.reg .u64 t; cvta.to.shared.u64 t, %1; cvt.u32.u64 %0, t;}" : "=r"(a) : "l"(p));
    return a;
}
__device__ __forceinline__ void ldsm4(unsigned& r0, unsigned& r1, unsigned& r2, unsigned& r3, unsigned a) {
    asm volatile("ldmatrix.sync.aligned.m8n8.x4.shared.b16 {%0,%1,%2,%3},[%4];\n"
                 : "=r"(r0), "=r"(r1), "=r"(r2), "=r"(r3) : "r"(a));
}
__device__ __forceinline__ void ldsm4t(unsigned& r0, unsigned& r1, unsigned& r2, unsigned& r3, unsigned a) {
    asm volatile("ldmatrix.sync.aligned.m8n8.x4.trans.shared.b16 {%0,%1,%2,%3},[%4];\n"
                 : "=r"(r0), "=r"(r1), "=r"(r2), "=r"(r3) : "r"(a));
}
__device__ __forceinline__ void mma16816(float* c, unsigned a0, unsigned a1, unsigned a2, unsigned a3,
                                         unsigned b0, unsigned b1) {
    asm volatile("mma.sync.aligned.m16n8k16.row.col.f32.f16.f16.f32 "
                 "{%0,%1,%2,%3},{%4,%5,%6,%7},{%8,%9},{%0,%1,%2,%3};\n"
                 : "+f"(c[0]), "+f"(c[1]), "+f"(c[2]), "+f"(c[3])
                 : "r"(a0), "r"(a1), "r"(a2), "r"(a3), "r"(b0), "r"(b1));
}

// ---------------------------------------------------------------------------
// fp32 -> fp16 converters
// ---------------------------------------------------------------------------
__global__ void __launch_bounds__(256) cvt_in(const float4* __restrict__ src, int which, int n4) {
    int i = blockIdx.x * 256 + threadIdx.x;
    if (i < n4) {
        float4 v = src[i];
        __half2 h0 = __floats2half2_rn(v.x, v.y);
        __half2 h1 = __floats2half2_rn(v.z, v.w);
        ((__half2*)g_A16[which])[i * 2]     = h0;
        ((__half2*)g_A16[which])[i * 2 + 1] = h1;
    }
}
__global__ void __launch_bounds__(256) cvt_w(const float4* __restrict__ src, int which, int n4) {
    int i = blockIdx.x * 256 + threadIdx.x;
    if (i < n4) {
        float4 v = src[i];
        __half2 h0 = __floats2half2_rn(v.x, v.y);
        __half2 h1 = __floats2half2_rn(v.z, v.w);
        ((__half2*)g_W16[which])[i * 2]     = h0;
        ((__half2*)g_W16[which])[i * 2 + 1] = h1;
    }
}

// ---------------------------------------------------------------------------
// Projection GEMM: C = A @ W^T + bias, out head-split fp16 [b,h,s,d].
// BM=128 BN=128 BK=32, 256 thr, warp grid 2x4, warp tile 64x32.
// ---------------------------------------------------------------------------
__global__ void __launch_bounds__(256) proj_gemm(int which, const float* __restrict__ bias) {
    const __half* A = g_A16[which];
    const __half* W = g_W16[which];
    __half* out = (which == 0) ? g_Kh : (which == 1) ? g_Qh : g_Vh;

    __shared__ union {
        struct { __half A[2][128][40]; __half B[2][128][40]; } t;
        __half C[128][136];
    } sh;

    const int tid = threadIdx.x;
    const int bm = blockIdx.y * 128, bn = blockIdx.x * 128;
    const int w = tid >> 5, l = tid & 31;
    const int wm = w >> 2, wn = w & 3;

    const int lrow = tid >> 1, lseg = (tid & 1) * 16;
    const __half* Ag = A + (size_t)(bm + lrow) * DD + lseg;
    const __half* Bg = W + (size_t)(bn + lrow) * DD + lseg;

    float acc[4][4][4];
#pragma unroll
    for (int mt = 0; mt < 4; mt++)
#pragma unroll
        for (int nt = 0; nt < 4; nt++)
#pragma unroll
            for (int r = 0; r < 4; r++) acc[mt][nt][r] = 0.f;

    const int a_r = l & 15, a_c = (l >> 4) * 8;
    const int b_r = (l & 7) | ((l >> 1) & 8), b_c = l & 8;
    const unsigned sA = sptr(&sh.t.A[0][0][0]);
    const unsigned sB = sptr(&sh.t.B[0][0][0]);
    const unsigned bufstride = 128 * 40 * 2;

    uint4 va0 = *(const uint4*)(Ag);
    uint4 va1 = *(const uint4*)(Ag + 8);
    uint4 vb0 = *(const uint4*)(Bg);
    uint4 vb1 = *(const uint4*)(Bg + 8);
    *(uint4*)&sh.t.A[0][lrow][lseg] = va0; *(uint4*)&sh.t.A[0][lrow][lseg + 8] = va1;
    *(uint4*)&sh.t.B[0][lrow][lseg] = vb0; *(uint4*)&sh.t.B[0][lrow][lseg + 8] = vb1;
    __syncthreads();

    for (int kb = 0; kb < DD / 32; kb++) {
        const int buf = kb & 1;
        if (kb + 1 < DD / 32) {
            const __half* An = Ag + (kb + 1) * 32;
            va0 = *(const uint4*)(An); va1 = *(const uint4*)(An + 8);
            const __half* Bn = Bg + (kb + 1) * 32;
            vb0 = *(const uint4*)(Bn); vb1 = *(const uint4*)(Bn + 8);
        }
#pragma unroll
        for (int ks = 0; ks < 2; ks++) {
            unsigned a[4][4], bfr[2][4];
#pragma unroll
            for (int mt = 0; mt < 4; mt++) {
                int r = wm * 64 + mt * 16 + a_r;
                int c = ks * 16 + a_c;
                ldsm4(a[mt][0], a[mt][1], a[mt][2], a[mt][3],
                      sA + buf * bufstride + (unsigned)(r * 40 + c) * 2);
            }
#pragma unroll
            for (int np = 0; np < 2; np++) {
                int r = wn * 32 + np * 16 + b_r;
                int c = ks * 16 + b_c;
                ldsm4(bfr[np][0], bfr[np][1], bfr[np][2], bfr[np][3],
                      sB + buf * bufstride + (unsigned)(r * 40 + c) * 2);
            }
#pragma unroll
            for (int mt = 0; mt < 4; mt++)
#pragma unroll
                for (int nt = 0; nt < 4; nt++)
                    mma16816(acc[mt][nt], a[mt][0], a[mt][1], a[mt][2], a[mt][3],
                             bfr[nt >> 1][(nt & 1) * 2], bfr[nt >> 1][(nt & 1) * 2 + 1]);
        }
        if (kb + 1 < DD / 32) {
            const int nb = buf ^ 1;
            *(uint4*)&sh.t.A[nb][lrow][lseg] = va0; *(uint4*)&sh.t.A[nb][lrow][lseg + 8] = va1;
            *(uint4*)&sh.t.B[nb][lrow][lseg] = vb0; *(uint4*)&sh.t.B[nb][lrow][lseg + 8] = vb1;
        }
        __syncthreads();
    }

    // stage C to smem with bias
#pragma unroll
    for (int nt = 0; nt < 4; nt++) {
        int c0 = wn * 32 + nt * 8 + 2 * (l & 3);
        float bv0 = bias[bn + c0], bv1 = bias[bn + c0 + 1];
#pragma unroll
        for (int mt = 0; mt < 4; mt++) {
            int r0 = wm * 64 + mt * 16 + (l >> 2);
            *(__half2*)&sh.C[r0][c0]     = __floats2half2_rn(acc[mt][nt][0] + bv0, acc[mt][nt][1] + bv1);
            *(__half2*)&sh.C[r0 + 8][c0] = __floats2half2_rn(acc[mt][nt][2] + bv0, acc[mt][nt][3] + bv1);
        }
    }
    __syncthreads();

    // head-split coalesced write
    const int h = tid & 15, sg = tid >> 4;
#pragma unroll
    for (int sl = 0; sl < 8; sl++) {
        int s = sg * 8 + sl;
        int m = bm + s;
        int b_ = m >> 11, sloc = m & 2047;
        __half tmp[8];
#pragma unroll
        for (int dd = 0; dd < 8; dd++) tmp[dd] = sh.C[s][h + 16 * dd];
        *(uint4*)&out[(((size_t)(b_ * NHH + h)) * SS + sloc) * DHH + (bn >> 4)] = *(uint4*)tmp;
    }
}

// ---------------------------------------------------------------------------
// Fused score + head-softmax. CTA: (b, 64 i keys, 64 k queries), 16 heads.
// Dynamic smem: Ksm[64][72], Qsm[64][72], Ssm[16][64][66].
// ---------------------------------------------------------------------------
__global__ void __launch_bounds__(256) score_softmax() {
    extern __shared__ __half smbuf[];
    __half* Ksm = smbuf;                 // 64*72
    __half* Qsm = smbuf + 64 * 72;       // 64*72
    __half* Ssm = smbuf + 2 * 64 * 72;   // 16*64*66

    const int b = blockIdx.z;
    const int ib = blockIdx.x * 64;
    const int kbq = blockIdx.y * 64;
    const int tid = threadIdx.x;
    const int w = tid >> 5, l = tid & 31;
    const int wm = w >> 2, wn = w & 3;

    const int lrow = tid >> 2, lseg = (tid & 3) * 16;
    const int a_r = l & 15, a_c = (l >> 4) * 8;
    const int b_r = (l & 7) | ((l >> 1) & 8), b_c = l & 8;
    const unsigned sK = sptr(Ksm);
    const unsigned sQ = sptr(Qsm);

    uint4 kv0, kv1, qv0, qv1;
    {
        const __half* Kg = g_Kh + (((size_t)(b * NHH + 0)) * SS + ib + lrow) * DHH + lseg;
        const __half* Qg = g_Qh + (((size_t)(b * NHH + 0)) * SS + kbq + lrow) * DHH + lseg;
        kv0 = *(const uint4*)Kg; kv1 = *(const uint4*)(Kg + 8);
        qv0 = *(const uint4*)Qg; qv1 = *(const uint4*)(Qg + 8);
    }

    for (int h = 0; h < NHH; h++) {
        *(uint4*)&Ksm[lrow * 72 + lseg] = kv0; *(uint4*)&Ksm[lrow * 72 + lseg + 8] = kv1;
        *(uint4*)&Qsm[lrow * 72 + lseg] = qv0; *(uint4*)&Qsm[lrow * 72 + lseg + 8] = qv1;
        __syncthreads();

        if (h + 1 < NHH) {
            const __half* Kg = g_Kh + (((size_t)(b * NHH + h + 1)) * SS + ib + lrow) * DHH + lseg;
            const __half* Qg = g_Qh + (((size_t)(b * NHH + h + 1)) * SS + kbq + lrow) * DHH + lseg;
            kv0 = *(const uint4*)Kg; kv1 = *(const uint4*)(Kg + 8);
            qv0 = *(const uint4*)Qg; qv1 = *(const uint4*)(Qg + 8);
        }

        float acc[2][2][4];
#pragma unroll
        for (int mt = 0; mt < 2; mt++)
#pragma unroll
            for (int nt = 0; nt < 2; nt++)
#pragma unroll
                for (int r = 0; r < 4; r++) acc[mt][nt][r] = 0.f;

#pragma unroll
        for (int ks = 0; ks < 4; ks++) {
            unsigned a[2][4], bf[4];
#pragma unroll
            for (int mt = 0; mt < 2; mt++) {
                int r = wm * 32 + mt * 16 + a_r;
                int c = ks * 16 + a_c;
                ldsm4(a[mt][0], a[mt][1], a[mt][2], a[mt][3], sK + (unsigned)(r * 72 + c) * 2);
            }
            {
                int r = wn * 16 + b_r;
                int c = ks * 16 + b_c;
                ldsm4(bf[0], bf[1], bf[2], bf[3], sQ + (unsigned)(r * 72 + c) * 2);
            }
#pragma unroll
            for (int mt = 0; mt < 2; mt++)
#pragma unroll
                for (int nt = 0; nt < 2; nt++)
                    mma16816(acc[mt][nt], a[mt][0], a[mt][1], a[mt][2], a[mt][3],
                             bf[nt * 2], bf[nt * 2 + 1]);
        }

        // stash scaled scores
#pragma unroll
        for (int mt = 0; mt < 2; mt++)
#pragma unroll
            for (int nt = 0; nt < 2; nt++) {
                int r = wm * 32 + mt * 16 + (l >> 2);
                int c = wn * 16 + nt * 8 + 2 * (l & 3);
                *(__half2*)&Ssm[h * 4224 + r * 66 + c] =
                    __floats2half2_rn(acc[mt][nt][0] * 0.125f, acc[mt][nt][1] * 0.125f);
                *(__half2*)&Ssm[h * 4224 + (r + 8) * 66 + c] =
                    __floats2half2_rn(acc[mt][nt][2] * 0.125f, acc[mt][nt][3] * 0.125f);
            }
        __syncthreads();
    }

    // phase 2: softmax over heads, write attn[b,h,k,i] fp16
    const int il = tid & 63;
    const int kgv = tid >> 6;
    const int b16 = b * NHH;
#pragma unroll 1
    for (int kk = 0; kk < 16; kk++) {
        const int kloc = kgv * 16 + kk;
        float v[NHH];
        float mx = -1e30f;
#pragma unroll
        for (int h2 = 0; h2 < NHH; h2++) {
            v[h2] = __half2float(Ssm[h2 * 4224 + il * 66 + kloc]);
            mx = fmaxf(mx, v[h2]);
        }
        float s = 0.f;
#pragma unroll
        for (int h2 = 0; h2 < NHH; h2++) {
            v[h2] = __expf(v[h2] - mx);
            s += v[h2];
        }
        const float inv = 1.f / s;
        const size_t kq = (size_t)(kbq + kloc);
#pragma unroll
        for (int h2 = 0; h2 < NHH; h2++) {
            g_attn[((size_t)(b16 + h2) * SS + kq) * SS + ib + il] = __float2half_rn(v[h2] * inv);
        }
    }
}

// ---------------------------------------------------------------------------
// AV GEMM per (b,h): Xt[b][16j+h][k] = sum_i attn[b,h,k,i] * Vh[b,h,i,j]
// CTA: 128 k x 64 j, K-loop i in 32-chunks. 8 warps 4x2, warp 32x32.
// ---------------------------------------------------------------------------
__global__ void __launch_bounds__(256) av_gemm() {
    const int z = blockIdx.y;
    const int b_ = z >> 4, hn = z & 15;
    const int kb0 = blockIdx.x * 128;
    const __half* Aattn = g_attn + (size_t)z * SS * SS;
    const __half* V = g_Vh + (size_t)z * SS * DHH;

    __shared__ __half Asm[2][128][40];
    __shared__ __half Bsm[2][32][72];

    const int tid = threadIdx.x;
    const int w = tid >> 5, l = tid & 31;
    const int wm = w >> 1, wn = w & 1;

    const int alrow = tid >> 1, alseg = (tid & 1) * 16;
    const int blrow = tid >> 3, blseg = (tid & 7) * 8;

    const int a_r = l & 15, a_c = (l >> 4) * 8;
    const int bt_r = (l & 7) + ((l >> 3) & 1) * 8;
    const int bt_c = ((l >> 4) & 1) * 8;

    const unsigned sA = sptr(&Asm[0][0][0]);
    const unsigned sB = sptr(&Bsm[0][0][0]);
    const unsigned Abs = 128 * 40 * 2, Bbs = 32 * 72 * 2;

    float acc[2][4][4];
#pragma unroll
    for (int mt = 0; mt < 2; mt++)
#pragma unroll
        for (int nt = 0; nt < 4; nt++)
#pragma unroll
            for (int r = 0; r < 4; r++) acc[mt][nt][r] = 0.f;

    const __half* Ag = Aattn + (size_t)(kb0 + alrow) * SS + alseg;
    const __half* Bg = V + (size_t)blrow * DHH + blseg;

    uint4 va0 = *(const uint4*)Ag;
    uint4 va1 = *(const uint4*)(Ag + 8);
    uint4 vb0 = *(const uint4*)Bg;
    *(uint4*)&Asm[0][alrow][alseg] = va0; *(uint4*)&Asm[0][alrow][alseg + 8] = va1;
    *(uint4*)&Bsm[0][blrow][blseg] = vb0;
    __syncthreads();

    for (int it = 0; it < SS / 32; it++) {
        const int buf = it & 1;
        if (it + 1 < SS / 32) {
            const __half* An = Ag + (it + 1) * 32;
            va0 = *(const uint4*)An; va1 = *(const uint4*)(An + 8);
            vb0 = *(const uint4*)(Bg + (size_t)(it + 1) * 32 * DHH);
        }
#pragma unroll
        for (int ks = 0; ks < 2; ks++) {
            unsigned a[2][4], bfr[2][4];
#pragma unroll
            for (int mt = 0; mt < 2; mt++) {
                int r = wm * 32 + mt * 16 + a_r;
                int c = ks * 16 + a_c;
                ldsm4(a[mt][0], a[mt][1], a[mt][2], a[mt][3],
                      sA + buf * Abs + (unsigned)(r * 40 + c) * 2);
            }
#pragma unroll
            for (int np = 0; np < 2; np++) {
                int r = ks * 16 + bt_r;
                int c = wn * 32 + np * 16 + bt_c;
                ldsm4t(bfr[np][0], bfr[np][1], bfr[np][2], bfr[np][3],
                       sB + buf * Bbs + (unsigned)(r * 72 + c) * 2);
            }
#pragma unroll
            for (int mt = 0; mt < 2; mt++)
#pragma unroll
                for (int nt = 0; nt < 4; nt++)
                    mma16816(acc[mt][nt], a[mt][0], a[mt][1], a[mt][2], a[mt][3],
                             bfr[nt >> 1][(nt & 1) * 2], bfr[nt >> 1][(nt & 1) * 2 + 1]);
        }
        if (it + 1 < SS / 32) {
            const int nb = buf ^ 1;
            *(uint4*)&Asm[nb][alrow][alseg] = va0; *(uint4*)&Asm[nb][alrow][alseg + 8] = va1;
            *(uint4*)&Bsm[nb][blrow][blseg] = vb0;
        }
        __syncthreads();
    }

    // epilogue: Xt[b][16j+h][k]
    __half* Xb = g_Xt + (size_t)b_ * HH * SS;
#pragma unroll
    for (int mt = 0; mt < 2; mt++) {
        int m0 = kb0 + wm * 32 + mt * 16 + (l >> 2);
#pragma unroll
        for (int nt = 0; nt < 4; nt++) {
            int j0 = wn * 32 + nt * 8 + 2 * (l & 3);
            Xb[(size_t)(16 * j0 + hn) * SS + m0]           = __float2half_rn(acc[mt][nt][0]);
            Xb[(size_t)(16 * (j0 + 1) + hn) * SS + m0]     = __float2half_rn(acc[mt][nt][1]);
            Xb[(size_t)(16 * j0 + hn) * SS + m0 + 8]       = __float2half_rn(acc[mt][nt][2]);
            Xb[(size_t)(16 * (j0 + 1) + hn) * SS + m0 + 8] = __float2half_rn(acc[mt][nt][3]);
        }
    }
}

// ---------------------------------------------------------------------------
// Output projection: out = X @ Wo^T + bias (fp32 out). A read from Xt via
// trans ldmatrix. BM=128 BN=128 BK=32.
// ---------------------------------------------------------------------------
__global__ void __launch_bounds__(256) outproj_gemm(const float* __restrict__ bias,
                                                    float* __restrict__ out) {
    const __half* Wo = g_W16[3];

    __shared__ __half At[2][32][136];
    __shared__ __half Bt[2][128][40];

    const int tid = threadIdx.x;
    const int bm = blockIdx.y * 128, bn = blockIdx.x * 128;
    const int b_ = bm >> 11, sbase = bm & 2047;
    const int w = tid >> 5, l = tid & 31;
    const int wm = w >> 2, wn = w & 3;

    const int arow = tid >> 3, aseg = (tid & 7) * 16;
    const int brow = tid >> 1, bseg = (tid & 1) * 16;

    const int at_r = (l & 7) + ((l >> 4) & 1) * 8;
    const int at_c = ((l >> 3) & 1) * 8;
    const int b_r = (l & 7) | ((l >> 1) & 8), b_c = l & 8;

    const unsigned sAt = sptr(&At[0][0][0]);
    const unsigned sBt = sptr(&Bt[0][0][0]);
    const unsigned Abs = 32 * 136 * 2, Bbs = 128 * 40 * 2;

    const __half* Ag = g_Xt + (size_t)b_ * HH * SS + (size_t)arow * SS + sbase + aseg;
    const __half* Bg = Wo + (size_t)(bn + brow) * HH + bseg;

    float acc[4][4][4];
#pragma unroll
    for (int mt = 0; mt < 4; mt++)
#pragma unroll
        for (int nt = 0; nt < 4; nt++)
#pragma unroll
            for (int r = 0; r < 4; r++) acc[mt][nt][r] = 0.f;

    uint4 va0 = *(const uint4*)Ag;
    uint4 va1 = *(const uint4*)(Ag + 8);
    uint4 vb0 = *(const uint4*)Bg;
    uint4 vb1 = *(const uint4*)(Bg + 8);
    *(uint4*)&At[0][arow][aseg] = va0; *(uint4*)&At[0][arow][aseg + 8] = va1;
    *(uint4*)&Bt[0][brow][bseg] = vb0; *(uint4*)&Bt[0][brow][bseg + 8] = vb1;
    __syncthreads();

    for (int kb = 0; kb < HH / 32; kb++) {
        const int buf = kb & 1;
        if (kb + 1 < HH / 32) {
            const __half* An = Ag + (size_t)(kb + 1) * 32 * SS;
            va0 = *(const uint4*)An; va1 = *(const uint4*)(An + 8);
            const __half* Bn = Bg + (kb + 1) * 32;
            vb0 = *(const uint4*)Bn; vb1 = *(const uint4*)(Bn + 8);
        }
#pragma unroll
        for (int ks = 0; ks < 2; ks++) {
            unsigned a[4][4], bfr[2][4];
#pragma unroll
            for (int mt = 0; mt < 4; mt++) {
                int r = ks * 16 + at_r;
                int c = wm * 64 + mt * 16 + at_c;
                ldsm4t(a[mt][0], a[mt][1], a[mt][2], a[mt][3],
                       sAt + buf * Abs + (unsigned)(r * 136 + c) * 2);
            }
#pragma unroll
            for (int np = 0; np < 2; np++) {
                int r = wn * 32 + np * 16 + b_r;
                int c = ks * 16 + b_c;
                ldsm4(bfr[np][0], bfr[np][1], bfr[np][2], bfr[np][3],
                      sBt + buf * Bbs + (unsigned)(r * 40 + c) * 2);
            }
#pragma unroll
            for (int mt = 0; mt < 4; mt++)
#pragma unroll
                for (int nt = 0; nt < 4; nt++)
                    mma16816(acc[mt][nt], a[mt][0], a[mt][1], a[mt][2], a[mt][3],
                             bfr[nt >> 1][(nt & 1) * 2], bfr[nt >> 1][(nt & 1) * 2 + 1]);
        }
        if (kb + 1 < HH / 32) {
            const int nb = buf ^ 1;
            *(uint4*)&At[nb][arow][aseg] = va0; *(uint4*)&At[nb][arow][aseg + 8] = va1;
            *(uint4*)&Bt[nb][brow][bseg] = vb0; *(uint4*)&Bt[nb][brow][bseg + 8] = vb1;
        }
        __syncthreads();
    }

#pragma unroll
    for (int nt = 0; nt < 4; nt++) {
        int c0 = bn + wn * 32 + nt * 8 + 2 * (l & 3);
        float bv0 = bias[c0], bv1 = bias[c0 + 1];
#pragma unroll
        for (int mt = 0; mt < 4; mt++) {
            int r0 = bm + wm * 64 + mt * 16 + (l >> 2);
            float2 v0 = make_float2(acc[mt][nt][0] + bv0, acc[mt][nt][1] + bv1);
            float2 v1 = make_float2(acc[mt][nt][2] + bv0, acc[mt][nt][3] + bv1);
            *(float2*)&out[(size_t)r0 * HH + c0] = v0;
            *(float2*)&out[(size_t)(r0 + 8) * HH + c0] = v1;
        }
    }
}

// ---------------------------------------------------------------------------
// Launch
// ---------------------------------------------------------------------------
extern "C" void kernel_launch(void* const* d_in, const int* in_sizes, int n_in,
                              void* d_out, int out_size)
{
    const float* KEY   = (const float*)d_in[0];
    const float* VALUE = (const float*)d_in[1];
    const float* QUERY = (const float*)d_in[2];
    const float* Wk_w  = (const float*)d_in[3];
    const float* Wk_b  = (const float*)d_in[4];
    const float* Wq_w  = (const float*)d_in[5];
    const float* Wq_b  = (const float*)d_in[6];
    const float* Wv_w  = (const float*)d_in[7];
    const float* Wv_b  = (const float*)d_in[8];
    const float* Wo_w  = (const float*)d_in[9];
    const float* Wo_b  = (const float*)d_in[10];
    float* out = (float*)d_out;

    static bool attr_done = false;
    if (!attr_done) {
        cudaFuncSetAttribute(score_softmax, cudaFuncAttributeMaxDynamicSharedMemorySize, 160000);
        attr_done = true;
    }

    const int nin4 = BB * SS * DD / 4;     // 1M float4
    const int nw4  = HH * DD / 4;          // 256K float4
    cvt_in<<<nin4 / 256, 256>>>((const float4*)KEY,   0, nin4);
    cvt_in<<<nin4 / 256, 256>>>((const float4*)QUERY, 1, nin4);
    cvt_in<<<nin4 / 256, 256>>>((const float4*)VALUE, 2, nin4);
    cvt_w<<<nw4 / 256, 256>>>((const float4*)Wk_w, 0, nw4);
    cvt_w<<<nw4 / 256, 256>>>((const float4*)Wq_w, 1, nw4);
    cvt_w<<<nw4 / 256, 256>>>((const float4*)Wv_w, 2, nw4);
    cvt_w<<<nw4 / 256, 256>>>((const float4*)Wo_w, 3, nw4);

    dim3 pg(HH / 128, (BB * SS) / 128);            // (8, 32)
    proj_gemm<<<pg, 256>>>(0, Wk_b);
    proj_gemm<<<pg, 256>>>(1, Wq_b);
    proj_gemm<<<pg, 256>>>(2, Wv_b);

    const int smbytes = (2 * 64 * 72 + 16 * 64 * 66) * 2;   // 153600
    dim3 sg(SS / 64, SS / 64, BB);                 // (32, 32, 2)
    score_softmax<<<sg, 256, smbytes>>>();

    dim3 ag(SS / 128, BB * NHH);                   // (16, 32)
    av_gemm<<<ag, 256>>>();

    dim3 og(HH / 128, (BB * SS) / 128);            // (8, 32)
    outproj_gemm<<<og, 256>>>(Wo_b, out);
}

// round 5
// speedup vs baseline: 4.6350x; 1.1288x over previous
#include <cuda_runtime.h>
#include <cuda_fp16.h>

#define BB  2
#define SS  2048
#define DD  1024
#define HH  1024
#define NHH 16
#define DHH 64

// ---------------------------------------------------------------------------
// Static scratch
// ---------------------------------------------------------------------------
__device__ __half g_A16[3][BB * SS * DD];          // fp16 KEY, QUERY, VALUE
__device__ __half g_W16[4][HH * DD];               // fp16 Wk, Wq, Wv, Wo
__device__ __half g_Kh[BB * NHH * SS * DHH];       // head-split projections
__device__ __half g_Qh[BB * NHH * SS * DHH];
__device__ __half g_Vh[BB * NHH * SS * DHH];
__device__ __half g_attn[(size_t)BB * NHH * SS * SS];   // attn [b,h,k,i]
__device__ __half g_Xt[BB * HH * SS];              // X transposed [b][c][s]

// ---------------------------------------------------------------------------
// PTX helpers
// ---------------------------------------------------------------------------
__device__ __forceinline__ unsigned sptr(const void* p) {
    unsigned a;
    asm("{.reg .u64 t; cvta.to.shared.u64 t, %1; cvt.u32.u64 %0, t;}" : "=r"(a) : "l"(p));
    return a;
}
__device__ __forceinline__ void ldsm4(unsigned& r0, unsigned& r1, unsigned& r2, unsigned& r3, unsigned a) {
    asm volatile("ldmatrix.sync.aligned.m8n8.x4.shared.b16 {%0,%1,%2,%3},[%4];\n"
                 : "=r"(r0), "=r"(r1), "=r"(r2), "=r"(r3) : "r"(a));
}
__device__ __forceinline__ void ldsm4t(unsigned& r0, unsigned& r1, unsigned& r2, unsigned& r3, unsigned a) {
    asm volatile("ldmatrix.sync.aligned.m8n8.x4.trans.shared.b16 {%0,%1,%2,%3},[%4];\n"
                 : "=r"(r0), "=r"(r1), "=r"(r2), "=r"(r3) : "r"(a));
}
__device__ __forceinline__ void mma16816(float* c, unsigned a0, unsigned a1, unsigned a2, unsigned a3,
                                         unsigned b0, unsigned b1) {
    asm volatile("mma.sync.aligned.m16n8k16.row.col.f32.f16.f16.f32 "
                 "{%0,%1,%2,%3},{%4,%5,%6,%7},{%8,%9},{%0,%1,%2,%3};\n"
                 : "+f"(c[0]), "+f"(c[1]), "+f"(c[2]), "+f"(c[3])
                 : "r"(a0), "r"(a1), "r"(a2), "r"(a3), "r"(b0), "r"(b1));
}
__device__ __forceinline__ void cpa16(unsigned d, const void* s) {
    asm volatile("cp.async.cg.shared.global [%0],[%1],16;\n" :: "r"(d), "l"(s));
}
__device__ __forceinline__ void cpa_commit() { asm volatile("cp.async.commit_group;\n"); }
template <int N> __device__ __forceinline__ void cpa_wait() {
    asm volatile("cp.async.wait_group %0;\n" :: "n"(N));
}

// ---------------------------------------------------------------------------
// Fused fp32->fp16 conversion for 3 inputs + 4 weights (one launch).
// ---------------------------------------------------------------------------
#define IN4 (BB * SS * DD / 4)
#define W4  (HH * DD / 4)
__global__ void __launch_bounds__(256) cvt_all(const float4* __restrict__ k,
                                               const float4* __restrict__ q,
                                               const float4* __restrict__ v,
                                               const float4* __restrict__ wk,
                                               const float4* __restrict__ wq,
                                               const float4* __restrict__ wv,
                                               const float4* __restrict__ wo)
{
    int idx = blockIdx.x * 256 + threadIdx.x;
    const float4* src;
    __half2* dst;
    int li;
    if (idx < 3 * IN4) {
        int which = idx / IN4;
        li = idx - which * IN4;
        src = (which == 0) ? k : (which == 1) ? q : v;
        dst = (__half2*)g_A16[which];
    } else {
        int r = idx - 3 * IN4;
        int which = r / W4;
        li = r - which * W4;
        src = (which == 0) ? wk : (which == 1) ? wq : (which == 2) ? wv : wo;
        dst = (__half2*)g_W16[which];
    }
    float4 val = src[li];
    dst[li * 2]     = __floats2half2_rn(val.x, val.y);
    dst[li * 2 + 1] = __floats2half2_rn(val.z, val.w);
}

// ---------------------------------------------------------------------------
// Projection GEMM: C = A @ W^T + bias, out head-split fp16 [b,h,s,d].
// BM=128 BN=128 BK=32, 256 thr, warp grid 2x4, warp tile 64x32.
// ---------------------------------------------------------------------------
__global__ void __launch_bounds__(256) proj_gemm(int which, const float* __restrict__ bias) {
    const __half* A = g_A16[which];
    const __half* W = g_W16[which];
    __half* out = (which == 0) ? g_Kh : (which == 1) ? g_Qh : g_Vh;

    __shared__ union {
        struct { __half A[2][128][40]; __half B[2][128][40]; } t;
        __half C[128][136];
    } sh;

    const int tid = threadIdx.x;
    const int bm = blockIdx.y * 128, bn = blockIdx.x * 128;
    const int w = tid >> 5, l = tid & 31;
    const int wm = w >> 2, wn = w & 3;

    const int lrow = tid >> 1, lseg = (tid & 1) * 16;
    const __half* Ag = A + (size_t)(bm + lrow) * DD + lseg;
    const __half* Bg = W + (size_t)(bn + lrow) * DD + lseg;

    float acc[4][4][4];
#pragma unroll
    for (int mt = 0; mt < 4; mt++)
#pragma unroll
        for (int nt = 0; nt < 4; nt++)
#pragma unroll
            for (int r = 0; r < 4; r++) acc[mt][nt][r] = 0.f;

    const int a_r = l & 15, a_c = (l >> 4) * 8;
    const int b_r = (l & 7) | ((l >> 1) & 8), b_c = l & 8;
    const unsigned sA = sptr(&sh.t.A[0][0][0]);
    const unsigned sB = sptr(&sh.t.B[0][0][0]);
    const unsigned bufstride = 128 * 40 * 2;

    uint4 va0 = *(const uint4*)(Ag);
    uint4 va1 = *(const uint4*)(Ag + 8);
    uint4 vb0 = *(const uint4*)(Bg);
    uint4 vb1 = *(const uint4*)(Bg + 8);
    *(uint4*)&sh.t.A[0][lrow][lseg] = va0; *(uint4*)&sh.t.A[0][lrow][lseg + 8] = va1;
    *(uint4*)&sh.t.B[0][lrow][lseg] = vb0; *(uint4*)&sh.t.B[0][lrow][lseg + 8] = vb1;
    __syncthreads();

    for (int kb = 0; kb < DD / 32; kb++) {
        const int buf = kb & 1;
        if (kb + 1 < DD / 32) {
            const __half* An = Ag + (kb + 1) * 32;
            va0 = *(const uint4*)(An); va1 = *(const uint4*)(An + 8);
            const __half* Bn = Bg + (kb + 1) * 32;
            vb0 = *(const uint4*)(Bn); vb1 = *(const uint4*)(Bn + 8);
        }
#pragma unroll
        for (int ks = 0; ks < 2; ks++) {
            unsigned a[4][4], bfr[2][4];
#pragma unroll
            for (int mt = 0; mt < 4; mt++) {
                int r = wm * 64 + mt * 16 + a_r;
                int c = ks * 16 + a_c;
                ldsm4(a[mt][0], a[mt][1], a[mt][2], a[mt][3],
                      sA + buf * bufstride + (unsigned)(r * 40 + c) * 2);
            }
#pragma unroll
            for (int np = 0; np < 2; np++) {
                int r = wn * 32 + np * 16 + b_r;
                int c = ks * 16 + b_c;
                ldsm4(bfr[np][0], bfr[np][1], bfr[np][2], bfr[np][3],
                      sB + buf * bufstride + (unsigned)(r * 40 + c) * 2);
            }
#pragma unroll
            for (int mt = 0; mt < 4; mt++)
#pragma unroll
                for (int nt = 0; nt < 4; nt++)
                    mma16816(acc[mt][nt], a[mt][0], a[mt][1], a[mt][2], a[mt][3],
                             bfr[nt >> 1][(nt & 1) * 2], bfr[nt >> 1][(nt & 1) * 2 + 1]);
        }
        if (kb + 1 < DD / 32) {
            const int nb = buf ^ 1;
            *(uint4*)&sh.t.A[nb][lrow][lseg] = va0; *(uint4*)&sh.t.A[nb][lrow][lseg + 8] = va1;
            *(uint4*)&sh.t.B[nb][lrow][lseg] = vb0; *(uint4*)&sh.t.B[nb][lrow][lseg + 8] = vb1;
        }
        __syncthreads();
    }

    // stage C to smem with bias
#pragma unroll
    for (int nt = 0; nt < 4; nt++) {
        int c0 = wn * 32 + nt * 8 + 2 * (l & 3);
        float bv0 = bias[bn + c0], bv1 = bias[bn + c0 + 1];
#pragma unroll
        for (int mt = 0; mt < 4; mt++) {
            int r0 = wm * 64 + mt * 16 + (l >> 2);
            *(__half2*)&sh.C[r0][c0]     = __floats2half2_rn(acc[mt][nt][0] + bv0, acc[mt][nt][1] + bv1);
            *(__half2*)&sh.C[r0 + 8][c0] = __floats2half2_rn(acc[mt][nt][2] + bv0, acc[mt][nt][3] + bv1);
        }
    }
    __syncthreads();

    // head-split coalesced write
    const int h = tid & 15, sg = tid >> 4;
#pragma unroll
    for (int sl = 0; sl < 8; sl++) {
        int s = sg * 8 + sl;
        int m = bm + s;
        int b_ = m >> 11, sloc = m & 2047;
        __half tmp[8];
#pragma unroll
        for (int dd = 0; dd < 8; dd++) tmp[dd] = sh.C[s][h + 16 * dd];
        *(uint4*)&out[(((size_t)(b_ * NHH + h)) * SS + sloc) * DHH + (bn >> 4)] = *(uint4*)tmp;
    }
}

// ---------------------------------------------------------------------------
// Fused score + head-softmax v2. CTA: (b, 64 i keys, 64 k queries), 16 heads.
// cp.async double-buffered K/Q per head; C layout [k][i]; coalesced uint4
// attn stores. Dynamic smem: Q[2][64][72], K[2][64][72], S[16][64][80].
// ---------------------------------------------------------------------------
__global__ void __launch_bounds__(256) score_softmax() {
    extern __shared__ __half smbuf[];
    __half* Qs = smbuf;                       // 2*64*72 halves
    __half* Ks = smbuf + 2 * 64 * 72;         // 2*64*72
    __half* Ss = smbuf + 4 * 64 * 72;         // 16*64*80

    const int b = blockIdx.z;
    const int ib = blockIdx.x * 64;     // i (key) base
    const int kbq = blockIdx.y * 64;    // k (query) base
    const int tid = threadIdx.x;
    const int w = tid >> 5, l = tid & 31;
    const int wm = w >> 2, wn = w & 3;

    const unsigned sQ = sptr(Qs);
    const unsigned sK = sptr(Ks);
    const unsigned bufQ = 64 * 72 * 2;

    // loader mapping: 512 16B chunks per matrix, 2 per thread
    const int c0 = tid, c1 = tid + 256;
    const int r0 = c0 >> 3, s0 = (c0 & 7) * 8;
    const int r1 = c1 >> 3, s1 = (c1 & 7) * 8;

    const int a_r = l & 15, a_c = (l >> 4) * 8;
    const int b_r = (l & 7) | ((l >> 1) & 8), b_c = l & 8;

    // issue K/Q loads for head h into buffer bf
    auto issue = [&](int h, int bf) {
        const __half* Qg = g_Qh + (((size_t)(b * NHH + h)) * SS + kbq) * DHH;
        const __half* Kg = g_Kh + (((size_t)(b * NHH + h)) * SS + ib) * DHH;
        cpa16(sQ + bf * bufQ + (unsigned)(r0 * 72 + s0) * 2, Qg + r0 * DHH + s0);
        cpa16(sQ + bf * bufQ + (unsigned)(r1 * 72 + s1) * 2, Qg + r1 * DHH + s1);
        cpa16(sK + bf * bufQ + (unsigned)(r0 * 72 + s0) * 2, Kg + r0 * DHH + s0);
        cpa16(sK + bf * bufQ + (unsigned)(r1 * 72 + s1) * 2, Kg + r1 * DHH + s1);
        cpa_commit();
    };

    issue(0, 0);
    issue(1, 1);

    for (int h = 0; h < NHH; h++) {
        const int bf = h & 1;
        // TAIL FIX: on the last head only one group is outstanding, so
        // wait_group 1 would NOT wait for it. Drain fully there.
        if (h == NHH - 1) cpa_wait<0>(); else cpa_wait<1>();
        __syncthreads();

        float acc[2][2][4];
#pragma unroll
        for (int mt = 0; mt < 2; mt++)
#pragma unroll
            for (int nt = 0; nt < 2; nt++)
#pragma unroll
                for (int r = 0; r < 4; r++) acc[mt][nt][r] = 0.f;

#pragma unroll
        for (int ks = 0; ks < 4; ks++) {
            unsigned a[2][4], bf4[4];
#pragma unroll
            for (int mt = 0; mt < 2; mt++) {
                int r = wm * 32 + mt * 16 + a_r;
                int c = ks * 16 + a_c;
                ldsm4(a[mt][0], a[mt][1], a[mt][2], a[mt][3],
                      sQ + bf * bufQ + (unsigned)(r * 72 + c) * 2);
            }
            {
                int r = wn * 16 + b_r;
                int c = ks * 16 + b_c;
                ldsm4(bf4[0], bf4[1], bf4[2], bf4[3],
                      sK + bf * bufQ + (unsigned)(r * 72 + c) * 2);
            }
#pragma unroll
            for (int mt = 0; mt < 2; mt++)
#pragma unroll
                for (int nt = 0; nt < 2; nt++)
                    mma16816(acc[mt][nt], a[mt][0], a[mt][1], a[mt][2], a[mt][3],
                             bf4[nt * 2], bf4[nt * 2 + 1]);
        }

        // store scaled scores: Ss[h][k][i], stride 80
#pragma unroll
        for (int mt = 0; mt < 2; mt++)
#pragma unroll
            for (int nt = 0; nt < 2; nt++) {
                int r = wm * 32 + mt * 16 + (l >> 2);        // k
                int c = wn * 16 + nt * 8 + 2 * (l & 3);      // i
                *(__half2*)&Ss[(h * 64 + r) * 80 + c] =
                    __floats2half2_rn(acc[mt][nt][0] * 0.125f, acc[mt][nt][1] * 0.125f);
                *(__half2*)&Ss[(h * 64 + r + 8) * 80 + c] =
                    __floats2half2_rn(acc[mt][nt][2] * 0.125f, acc[mt][nt][3] * 0.125f);
            }
        __syncthreads();
        if (h + 2 < NHH) issue(h + 2, bf);
    }

    // softmax over heads at each (k,i); normalize in place
#pragma unroll 1
    for (int it = 0; it < 16; it++) {
        int p = it * 256 + tid;
        int kq = p >> 6, iq = p & 63;
        float v[NHH];
        float mx = -1e30f;
#pragma unroll
        for (int h2 = 0; h2 < NHH; h2++) {
            v[h2] = __half2float(Ss[(h2 * 64 + kq) * 80 + iq]);
            mx = fmaxf(mx, v[h2]);
        }
        float sum = 0.f;
#pragma unroll
        for (int h2 = 0; h2 < NHH; h2++) {
            v[h2] = __expf(v[h2] - mx);
            sum += v[h2];
        }
        float inv = 1.f / sum;
#pragma unroll
        for (int h2 = 0; h2 < NHH; h2++)
            Ss[(h2 * 64 + kq) * 80 + iq] = __float2half_rn(v[h2] * inv);
    }
    __syncthreads();

    // coalesced vectorized writeout: attn[b,h,k,i]
    const int hh = tid >> 4, sub = tid & 15;
    const size_t base = ((size_t)(b * NHH + hh) * SS + kbq) * SS + ib;
#pragma unroll 1
    for (int m = 0; m < 32; m++) {
        int vid = m * 16 + sub;            // k*8 + ig
        int kq = vid >> 3, ig = vid & 7;
        uint4 val = *(const uint4*)&Ss[(hh * 64 + kq) * 80 + ig * 8];
        *(uint4*)&g_attn[base + (size_t)kq * SS + ig * 8] = val;
    }
}

// ---------------------------------------------------------------------------
// AV GEMM per (b,h): Xt[b][16j+h][k] = sum_i attn[b,h,k,i] * Vh[b,h,i,j]
// 3-stage cp.async pipeline, CTA: 128 k x 64 j, i-chunks of 32.
// ---------------------------------------------------------------------------
__global__ void __launch_bounds__(256) av_gemm() {
    const int z = blockIdx.y;
    const int b_ = z >> 4, hn = z & 15;
    const int kb0 = blockIdx.x * 128;
    const __half* Aattn = g_attn + (size_t)z * SS * SS;
    const __half* V = g_Vh + (size_t)z * SS * DHH;

    __shared__ __half Asm[3][128][40];
    __shared__ __half Bsm[3][32][72];

    const int tid = threadIdx.x;
    const int w = tid >> 5, l = tid & 31;
    const int wm = w >> 1, wn = w & 1;

    // A loader: 512 chunks (2/thread): row (128), seg
    const int ac0 = tid, ac1 = tid + 256;
    const int ar0 = ac0 >> 2, as0 = (ac0 & 3) * 8;
    const int ar1 = ac1 >> 2, as1 = (ac1 & 3) * 8;
    // V loader: 256 chunks (1/thread)
    const int vr = tid >> 3, vs = (tid & 7) * 8;

    const int a_r = l & 15, a_c = (l >> 4) * 8;
    const int bt_r = (l & 7) + ((l >> 3) & 1) * 8;
    const int bt_c = ((l >> 4) & 1) * 8;

    const unsigned sA = sptr(&Asm[0][0][0]);
    const unsigned sB = sptr(&Bsm[0][0][0]);
    const unsigned Abs = 128 * 40 * 2, Bbs = 32 * 72 * 2;

    auto issue = [&](int it, int st) {
        const __half* Ag = Aattn + (size_t)kb0 * SS + it * 32;
        cpa16(sA + st * Abs + (unsigned)(ar0 * 40 + as0) * 2, Ag + (size_t)ar0 * SS + as0);
        cpa16(sA + st * Abs + (unsigned)(ar1 * 40 + as1) * 2, Ag + (size_t)ar1 * SS + as1);
        cpa16(sB + st * Bbs + (unsigned)(vr * 72 + vs) * 2, V + (size_t)(it * 32 + vr) * DHH + vs);
        cpa_commit();
    };

    float acc[2][4][4];
#pragma unroll
    for (int mt = 0; mt < 2; mt++)
#pragma unroll
        for (int nt = 0; nt < 4; nt++)
#pragma unroll
            for (int r = 0; r < 4; r++) acc[mt][nt][r] = 0.f;

    issue(0, 0);
    issue(1, 1);

    const int NIT = SS / 32;
    for (int it = 0; it < NIT; it++) {
        const int st = it % 3;
        // TAIL FIX: final iteration has only its own group outstanding.
        if (it == NIT - 1) cpa_wait<0>(); else cpa_wait<1>();
        __syncthreads();
        if (it + 2 < NIT) issue(it + 2, (it + 2) % 3);

#pragma unroll
        for (int ks = 0; ks < 2; ks++) {
            unsigned a[2][4], bfr[2][4];
#pragma unroll
            for (int mt = 0; mt < 2; mt++) {
                int r = wm * 32 + mt * 16 + a_r;
                int c = ks * 16 + a_c;
                ldsm4(a[mt][0], a[mt][1], a[mt][2], a[mt][3],
                      sA + st * Abs + (unsigned)(r * 40 + c) * 2);
            }
#pragma unroll
            for (int np = 0; np < 2; np++) {
                int r = ks * 16 + bt_r;
                int c = wn * 32 + np * 16 + bt_c;
                ldsm4t(bfr[np][0], bfr[np][1], bfr[np][2], bfr[np][3],
                       sB + st * Bbs + (unsigned)(r * 72 + c) * 2);
            }
#pragma unroll
            for (int mt = 0; mt < 2; mt++)
#pragma unroll
                for (int nt = 0; nt < 4; nt++)
                    mma16816(acc[mt][nt], a[mt][0], a[mt][1], a[mt][2], a[mt][3],
                             bfr[nt >> 1][(nt & 1) * 2], bfr[nt >> 1][(nt & 1) * 2 + 1]);
        }
    }

    // epilogue: Xt[b][16j+h][k]
    __half* Xb = g_Xt + (size_t)b_ * HH * SS;
#pragma unroll
    for (int mt = 0; mt < 2; mt++) {
        int m0 = kb0 + wm * 32 + mt * 16 + (l >> 2);
#pragma unroll
        for (int nt = 0; nt < 4; nt++) {
            int j0 = wn * 32 + nt * 8 + 2 * (l & 3);
            Xb[(size_t)(16 * j0 + hn) * SS + m0]           = __float2half_rn(acc[mt][nt][0]);
            Xb[(size_t)(16 * (j0 + 1) + hn) * SS + m0]     = __float2half_rn(acc[mt][nt][1]);
            Xb[(size_t)(16 * j0 + hn) * SS + m0 + 8]       = __float2half_rn(acc[mt][nt][2]);
            Xb[(size_t)(16 * (j0 + 1) + hn) * SS + m0 + 8] = __float2half_rn(acc[mt][nt][3]);
        }
    }
}

// ---------------------------------------------------------------------------
// Output projection: out = X @ Wo^T + bias (fp32 out). A read from Xt via
// trans ldmatrix. BM=128 BN=128 BK=32.
// ---------------------------------------------------------------------------
__global__ void __launch_bounds__(256) outproj_gemm(const float* __restrict__ bias,
                                                    float* __restrict__ out) {
    const __half* Wo = g_W16[3];

    __shared__ __half At[2][32][136];
    __shared__ __half Bt[2][128][40];

    const int tid = threadIdx.x;
    const int bm = blockIdx.y * 128, bn = blockIdx.x * 128;
    const int b_ = bm >> 11, sbase = bm & 2047;
    const int w = tid >> 5, l = tid & 31;
    const int wm = w >> 2, wn = w & 3;

    const int arow = tid >> 3, aseg = (tid & 7) * 16;
    const int brow = tid >> 1, bseg = (tid & 1) * 16;

    const int at_r = (l & 7) + ((l >> 4) & 1) * 8;
    const int at_c = ((l >> 3) & 1) * 8;
    const int b_r = (l & 7) | ((l >> 1) & 8), b_c = l & 8;

    const unsigned sAt = sptr(&At[0][0][0]);
    const unsigned sBt = sptr(&Bt[0][0][0]);
    const unsigned Abs = 32 * 136 * 2, Bbs = 128 * 40 * 2;

    const __half* Ag = g_Xt + (size_t)b_ * HH * SS + (size_t)arow * SS + sbase + aseg;
    const __half* Bg = Wo + (size_t)(bn + brow) * HH + bseg;

    float acc[4][4][4];
#pragma unroll
    for (int mt = 0; mt < 4; mt++)
#pragma unroll
        for (int nt = 0; nt < 4; nt++)
#pragma unroll
            for (int r = 0; r < 4; r++) acc[mt][nt][r] = 0.f;

    uint4 va0 = *(const uint4*)Ag;
    uint4 va1 = *(const uint4*)(Ag + 8);
    uint4 vb0 = *(const uint4*)Bg;
    uint4 vb1 = *(const uint4*)(Bg + 8);
    *(uint4*)&At[0][arow][aseg] = va0; *(uint4*)&At[0][arow][aseg + 8] = va1;
    *(uint4*)&Bt[0][brow][bseg] = vb0; *(uint4*)&Bt[0][brow][bseg + 8] = vb1;
    __syncthreads();

    for (int kb = 0; kb < HH / 32; kb++) {
        const int buf = kb & 1;
        if (kb + 1 < HH / 32) {
            const __half* An = Ag + (size_t)(kb + 1) * 32 * SS;
            va0 = *(const uint4*)An; va1 = *(const uint4*)(An + 8);
            const __half* Bn = Bg + (kb + 1) * 32;
            vb0 = *(const uint4*)Bn; vb1 = *(const uint4*)(Bn + 8);
        }
#pragma unroll
        for (int ks = 0; ks < 2; ks++) {
            unsigned a[4][4], bfr[2][4];
#pragma unroll
            for (int mt = 0; mt < 4; mt++) {
                int r = ks * 16 + at_r;
                int c = wm * 64 + mt * 16 + at_c;
                ldsm4t(a[mt][0], a[mt][1], a[mt][2], a[mt][3],
                       sAt + buf * Abs + (unsigned)(r * 136 + c) * 2);
            }
#pragma unroll
            for (int np = 0; np < 2; np++) {
                int r = wn * 32 + np * 16 + b_r;
                int c = ks * 16 + b_c;
                ldsm4(bfr[np][0], bfr[np][1], bfr[np][2], bfr[np][3],
                      sBt + buf * Bbs + (unsigned)(r * 40 + c) * 2);
            }
#pragma unroll
            for (int mt = 0; mt < 4; mt++)
#pragma unroll
                for (int nt = 0; nt < 4; nt++)
                    mma16816(acc[mt][nt], a[mt][0], a[mt][1], a[mt][2], a[mt][3],
                             bfr[nt >> 1][(nt & 1) * 2], bfr[nt >> 1][(nt & 1) * 2 + 1]);
        }
        if (kb + 1 < HH / 32) {
            const int nb = buf ^ 1;
            *(uint4*)&At[nb][arow][aseg] = va0; *(uint4*)&At[nb][arow][aseg + 8] = va1;
            *(uint4*)&Bt[nb][brow][bseg] = vb0; *(uint4*)&Bt[nb][brow][bseg + 8] = vb1;
        }
        __syncthreads();
    }

#pragma unroll
    for (int nt = 0; nt < 4; nt++) {
        int c0 = bn + wn * 32 + nt * 8 + 2 * (l & 3);
        float bv0 = bias[c0], bv1 = bias[c0 + 1];
#pragma unroll
        for (int mt = 0; mt < 4; mt++) {
            int r0 = bm + wm * 64 + mt * 16 + (l >> 2);
            float2 v0 = make_float2(acc[mt][nt][0] + bv0, acc[mt][nt][1] + bv1);
            float2 v1 = make_float2(acc[mt][nt][2] + bv0, acc[mt][nt][3] + bv1);
            *(float2*)&out[(size_t)r0 * HH + c0] = v0;
            *(float2*)&out[(size_t)(r0 + 8) * HH + c0] = v1;
        }
    }
}

// ---------------------------------------------------------------------------
// Launch
// ---------------------------------------------------------------------------
extern "C" void kernel_launch(void* const* d_in, const int* in_sizes, int n_in,
                              void* d_out, int out_size)
{
    const float* KEY   = (const float*)d_in[0];
    const float* VALUE = (const float*)d_in[1];
    const float* QUERY = (const float*)d_in[2];
    const float* Wk_w  = (const float*)d_in[3];
    const float* Wk_b  = (const float*)d_in[4];
    const float* Wq_w  = (const float*)d_in[5];
    const float* Wq_b  = (const float*)d_in[6];
    const float* Wv_w  = (const float*)d_in[7];
    const float* Wv_b  = (const float*)d_in[8];
    const float* Wo_w  = (const float*)d_in[9];
    const float* Wo_b  = (const float*)d_in[10];
    float* out = (float*)d_out;

    static bool attr_done = false;
    if (!attr_done) {
        cudaFuncSetAttribute(score_softmax, cudaFuncAttributeMaxDynamicSharedMemorySize, 210000);
        attr_done = true;
    }

    const int total4 = 3 * IN4 + 4 * W4;           // 4,194,304
    cvt_all<<<total4 / 256, 256>>>((const float4*)KEY, (const float4*)QUERY,
                                   (const float4*)VALUE, (const float4*)Wk_w,
                                   (const float4*)Wq_w, (const float4*)Wv_w,
                                   (const float4*)Wo_w);

    dim3 pg(HH / 128, (BB * SS) / 128);            // (8, 32)
    proj_gemm<<<pg, 256>>>(0, Wk_b);
    proj_gemm<<<pg, 256>>>(1, Wq_b);
    proj_gemm<<<pg, 256>>>(2, Wv_b);

    const int smbytes = (4 * 64 * 72 + 16 * 64 * 80) * 2;   // 200,704
    dim3 sg(SS / 64, SS / 64, BB);                 // (32, 32, 2)
    score_softmax<<<sg, 256, smbytes>>>();

    dim3 ag(SS / 128, BB * NHH);                   // (16, 32)
    av_gemm<<<ag, 256>>>();

    dim3 og(HH / 128, (BB * SS) / 128);            // (8, 32)
    outproj_gemm<<<og, 256>>>(Wo_b, out);
}

// round 6
// speedup vs baseline: 4.7708x; 1.0293x over previous
#include <cuda_runtime.h>
#include <cuda_fp16.h>

#define BB  2
#define SS  2048
#define DD  1024
#define HH  1024
#define NHH 16
#define DHH 64

// ---------------------------------------------------------------------------
// Static scratch
// ---------------------------------------------------------------------------
__device__ __half g_A16[3][BB * SS * DD];          // fp16 KEY, QUERY, VALUE
__device__ __half g_W16[4][HH * DD];               // fp16 Wk, Wq, Wv, Wo
__device__ __half g_Kh[BB * NHH * SS * DHH];       // head-split projections
__device__ __half g_Qh[BB * NHH * SS * DHH];
__device__ __half g_Vh[BB * NHH * SS * DHH];
__device__ __half g_attn[(size_t)BB * NHH * SS * SS];   // attn [b,h,k,i]
__device__ __half g_Xt[BB * HH * SS];              // X transposed [b][c][s]

// ---------------------------------------------------------------------------
// PTX helpers
// ---------------------------------------------------------------------------
__device__ __forceinline__ unsigned sptr(const void* p) {
    unsigned a;
    asm("{.reg .u64 t; cvta.to.shared.u64 t, %1; cvt.u32.u64 %0, t;}" : "=r"(a) : "l"(p));
    return a;
}
__device__ __forceinline__ void ldsm4(unsigned& r0, unsigned& r1, unsigned& r2, unsigned& r3, unsigned a) {
    asm volatile("ldmatrix.sync.aligned.m8n8.x4.shared.b16 {%0,%1,%2,%3},[%4];\n"
                 : "=r"(r0), "=r"(r1), "=r"(r2), "=r"(r3) : "r"(a));
}
__device__ __forceinline__ void ldsm4t(unsigned& r0, unsigned& r1, unsigned& r2, unsigned& r3, unsigned a) {
    asm volatile("ldmatrix.sync.aligned.m8n8.x4.trans.shared.b16 {%0,%1,%2,%3},[%4];\n"
                 : "=r"(r0), "=r"(r1), "=r"(r2), "=r"(r3) : "r"(a));
}
__device__ __forceinline__ void mma16816(float* c, unsigned a0, unsigned a1, unsigned a2, unsigned a3,
                                         unsigned b0, unsigned b1) {
    asm volatile("mma.sync.aligned.m16n8k16.row.col.f32.f16.f16.f32 "
                 "{%0,%1,%2,%3},{%4,%5,%6,%7},{%8,%9},{%0,%1,%2,%3};\n"
                 : "+f"(c[0]), "+f"(c[1]), "+f"(c[2]), "+f"(c[3])
                 : "r"(a0), "r"(a1), "r"(a2), "r"(a3), "r"(b0), "r"(b1));
}
__device__ __forceinline__ void cpa16(unsigned d, const void* s) {
    asm volatile("cp.async.cg.shared.global [%0],[%1],16;\n" :: "r"(d), "l"(s));
}
__device__ __forceinline__ void cpa_commit() { asm volatile("cp.async.commit_group;\n"); }
template <int N> __device__ __forceinline__ void cpa_wait() {
    asm volatile("cp.async.wait_group %0;\n" :: "n"(N));
}

// ---------------------------------------------------------------------------
// Fused fp32->fp16 conversion for 3 inputs + 4 weights (one launch).
// ---------------------------------------------------------------------------
#define IN4 (BB * SS * DD / 4)
#define W4  (HH * DD / 4)
__global__ void __launch_bounds__(256) cvt_all(const float4* __restrict__ k,
                                               const float4* __restrict__ q,
                                               const float4* __restrict__ v,
                                               const float4* __restrict__ wk,
                                               const float4* __restrict__ wq,
                                               const float4* __restrict__ wv,
                                               const float4* __restrict__ wo)
{
    int idx = blockIdx.x * 256 + threadIdx.x;
    const float4* src;
    __half2* dst;
    int li;
    if (idx < 3 * IN4) {
        int which = idx / IN4;
        li = idx - which * IN4;
        src = (which == 0) ? k : (which == 1) ? q : v;
        dst = (__half2*)g_A16[which];
    } else {
        int r = idx - 3 * IN4;
        int which = r / W4;
        li = r - which * W4;
        src = (which == 0) ? wk : (which == 1) ? wq : (which == 2) ? wv : wo;
        dst = (__half2*)g_W16[which];
    }
    float4 val = src[li];
    dst[li * 2]     = __floats2half2_rn(val.x, val.y);
    dst[li * 2 + 1] = __floats2half2_rn(val.z, val.w);
}

// ---------------------------------------------------------------------------
// Fused projection GEMM (K, Q, V in one launch; which = blockIdx.z).
// C = A @ W^T + bias, out head-split fp16 [b,h,s,d].
// BM=128 BN=128 BK=32, 256 thr, warp grid 2x4, warp tile 64x32.
// 3-stage cp.async pipeline.
// ---------------------------------------------------------------------------
__global__ void __launch_bounds__(256) proj_fused(const float* __restrict__ bk,
                                                  const float* __restrict__ bq,
                                                  const float* __restrict__ bv) {
    const int which = blockIdx.z;
    const __half* A = g_A16[which];
    const __half* W = g_W16[which];
    __half* out = (which == 0) ? g_Kh : (which == 1) ? g_Qh : g_Vh;
    const float* bias = (which == 0) ? bk : (which == 1) ? bq : bv;

    __shared__ union {
        __half t[3][2][128][40];   // [stage][A=0/B=1][row][col(pad)]
        __half C[128][136];
    } sh;

    const int tid = threadIdx.x;
    const int bm = blockIdx.y * 128, bn = blockIdx.x * 128;
    const int w = tid >> 5, l = tid & 31;
    const int wm = w >> 2, wn = w & 3;

    // loader mapping: 512 16B chunks per matrix, 2 per thread
    const int c0 = tid, c1 = tid + 256;
    const int ar0 = c0 >> 2, as0 = (c0 & 3) * 8;
    const int ar1 = c1 >> 2, as1 = (c1 & 3) * 8;

    const unsigned sBase = sptr(&sh.t[0][0][0][0]);
    const unsigned stgStride = 2 * 128 * 40 * 2;       // bytes per stage
    const unsigned bOff = 128 * 40 * 2;                // B offset within stage

    auto issue = [&](int kb, int st) {
        const __half* Ag = A + (size_t)(bm + 0) * DD + kb * 32;
        const __half* Bg = W + (size_t)(bn + 0) * DD + kb * 32;
        unsigned s = sBase + st * stgStride;
        cpa16(s + (unsigned)(ar0 * 40 + as0) * 2, Ag + (size_t)ar0 * DD + as0);
        cpa16(s + (unsigned)(ar1 * 40 + as1) * 2, Ag + (size_t)ar1 * DD + as1);
        cpa16(s + bOff + (unsigned)(ar0 * 40 + as0) * 2, Bg + (size_t)ar0 * DD + as0);
        cpa16(s + bOff + (unsigned)(ar1 * 40 + as1) * 2, Bg + (size_t)ar1 * DD + as1);
        cpa_commit();
    };

    float acc[4][4][4];
#pragma unroll
    for (int mt = 0; mt < 4; mt++)
#pragma unroll
        for (int nt = 0; nt < 4; nt++)
#pragma unroll
            for (int r = 0; r < 4; r++) acc[mt][nt][r] = 0.f;

    const int a_r = l & 15, a_c = (l >> 4) * 8;
    const int b_r = (l & 7) | ((l >> 1) & 8), b_c = l & 8;

    issue(0, 0);
    issue(1, 1);

    const int NKB = DD / 32;
    for (int kb = 0; kb < NKB; kb++) {
        const int st = kb % 3;
        if (kb == NKB - 1) cpa_wait<0>(); else cpa_wait<1>();
        __syncthreads();
        if (kb + 2 < NKB) issue(kb + 2, (kb + 2) % 3);

        const unsigned sA = sBase + st * stgStride;
        const unsigned sB = sA + bOff;
#pragma unroll
        for (int ks = 0; ks < 2; ks++) {
            unsigned a[4][4], bfr[2][4];
#pragma unroll
            for (int mt = 0; mt < 4; mt++) {
                int r = wm * 64 + mt * 16 + a_r;
                int c = ks * 16 + a_c;
                ldsm4(a[mt][0], a[mt][1], a[mt][2], a[mt][3],
                      sA + (unsigned)(r * 40 + c) * 2);
            }
#pragma unroll
            for (int np = 0; np < 2; np++) {
                int r = wn * 32 + np * 16 + b_r;
                int c = ks * 16 + b_c;
                ldsm4(bfr[np][0], bfr[np][1], bfr[np][2], bfr[np][3],
                      sB + (unsigned)(r * 40 + c) * 2);
            }
#pragma unroll
            for (int mt = 0; mt < 4; mt++)
#pragma unroll
                for (int nt = 0; nt < 4; nt++)
                    mma16816(acc[mt][nt], a[mt][0], a[mt][1], a[mt][2], a[mt][3],
                             bfr[nt >> 1][(nt & 1) * 2], bfr[nt >> 1][(nt & 1) * 2 + 1]);
        }
    }
    __syncthreads();   // everyone done with tiles before reusing union as C

    // stage C to smem with bias
#pragma unroll
    for (int nt = 0; nt < 4; nt++) {
        int c0v = wn * 32 + nt * 8 + 2 * (l & 3);
        float bv0 = bias[bn + c0v], bv1 = bias[bn + c0v + 1];
#pragma unroll
        for (int mt = 0; mt < 4; mt++) {
            int r0 = wm * 64 + mt * 16 + (l >> 2);
            *(__half2*)&sh.C[r0][c0v]     = __floats2half2_rn(acc[mt][nt][0] + bv0, acc[mt][nt][1] + bv1);
            *(__half2*)&sh.C[r0 + 8][c0v] = __floats2half2_rn(acc[mt][nt][2] + bv0, acc[mt][nt][3] + bv1);
        }
    }
    __syncthreads();

    // head-split coalesced write
    const int h = tid & 15, sg = tid >> 4;
#pragma unroll
    for (int sl = 0; sl < 8; sl++) {
        int s = sg * 8 + sl;
        int m = bm + s;
        int b_ = m >> 11, sloc = m & 2047;
        __half tmp[8];
#pragma unroll
        for (int dd = 0; dd < 8; dd++) tmp[dd] = sh.C[s][h + 16 * dd];
        *(uint4*)&out[(((size_t)(b_ * NHH + h)) * SS + sloc) * DHH + (bn >> 4)] = *(uint4*)tmp;
    }
}

// ---------------------------------------------------------------------------
// Fused score + head-softmax v2. CTA: (b, 64 i keys, 64 k queries), 16 heads.
// ---------------------------------------------------------------------------
__global__ void __launch_bounds__(256) score_softmax() {
    extern __shared__ __half smbuf[];
    __half* Qs = smbuf;                       // 2*64*72 halves
    __half* Ks = smbuf + 2 * 64 * 72;         // 2*64*72
    __half* Ss = smbuf + 4 * 64 * 72;         // 16*64*80

    const int b = blockIdx.z;
    const int ib = blockIdx.x * 64;     // i (key) base
    const int kbq = blockIdx.y * 64;    // k (query) base
    const int tid = threadIdx.x;
    const int w = tid >> 5, l = tid & 31;
    const int wm = w >> 2, wn = w & 3;

    const unsigned sQ = sptr(Qs);
    const unsigned sK = sptr(Ks);
    const unsigned bufQ = 64 * 72 * 2;

    const int c0 = tid, c1 = tid + 256;
    const int r0 = c0 >> 3, s0 = (c0 & 7) * 8;
    const int r1 = c1 >> 3, s1 = (c1 & 7) * 8;

    const int a_r = l & 15, a_c = (l >> 4) * 8;
    const int b_r = (l & 7) | ((l >> 1) & 8), b_c = l & 8;

    auto issue = [&](int h, int bf) {
        const __half* Qg = g_Qh + (((size_t)(b * NHH + h)) * SS + kbq) * DHH;
        const __half* Kg = g_Kh + (((size_t)(b * NHH + h)) * SS + ib) * DHH;
        cpa16(sQ + bf * bufQ + (unsigned)(r0 * 72 + s0) * 2, Qg + r0 * DHH + s0);
        cpa16(sQ + bf * bufQ + (unsigned)(r1 * 72 + s1) * 2, Qg + r1 * DHH + s1);
        cpa16(sK + bf * bufQ + (unsigned)(r0 * 72 + s0) * 2, Kg + r0 * DHH + s0);
        cpa16(sK + bf * bufQ + (unsigned)(r1 * 72 + s1) * 2, Kg + r1 * DHH + s1);
        cpa_commit();
    };

    issue(0, 0);
    issue(1, 1);

    for (int h = 0; h < NHH; h++) {
        const int bf = h & 1;
        if (h == NHH - 1) cpa_wait<0>(); else cpa_wait<1>();
        __syncthreads();

        float acc[2][2][4];
#pragma unroll
        for (int mt = 0; mt < 2; mt++)
#pragma unroll
            for (int nt = 0; nt < 2; nt++)
#pragma unroll
                for (int r = 0; r < 4; r++) acc[mt][nt][r] = 0.f;

#pragma unroll
        for (int ks = 0; ks < 4; ks++) {
            unsigned a[2][4], bf4[4];
#pragma unroll
            for (int mt = 0; mt < 2; mt++) {
                int r = wm * 32 + mt * 16 + a_r;
                int c = ks * 16 + a_c;
                ldsm4(a[mt][0], a[mt][1], a[mt][2], a[mt][3],
                      sQ + bf * bufQ + (unsigned)(r * 72 + c) * 2);
            }
            {
                int r = wn * 16 + b_r;
                int c = ks * 16 + b_c;
                ldsm4(bf4[0], bf4[1], bf4[2], bf4[3],
                      sK + bf * bufQ + (unsigned)(r * 72 + c) * 2);
            }
#pragma unroll
            for (int mt = 0; mt < 2; mt++)
#pragma unroll
                for (int nt = 0; nt < 2; nt++)
                    mma16816(acc[mt][nt], a[mt][0], a[mt][1], a[mt][2], a[mt][3],
                             bf4[nt * 2], bf4[nt * 2 + 1]);
        }

#pragma unroll
        for (int mt = 0; mt < 2; mt++)
#pragma unroll
            for (int nt = 0; nt < 2; nt++) {
                int r = wm * 32 + mt * 16 + (l >> 2);        // k
                int c = wn * 16 + nt * 8 + 2 * (l & 3);      // i
                *(__half2*)&Ss[(h * 64 + r) * 80 + c] =
                    __floats2half2_rn(acc[mt][nt][0] * 0.125f, acc[mt][nt][1] * 0.125f);
                *(__half2*)&Ss[(h * 64 + r + 8) * 80 + c] =
                    __floats2half2_rn(acc[mt][nt][2] * 0.125f, acc[mt][nt][3] * 0.125f);
            }
        __syncthreads();
        if (h + 2 < NHH) issue(h + 2, bf);
    }

#pragma unroll 1
    for (int it = 0; it < 16; it++) {
        int p = it * 256 + tid;
        int kq = p >> 6, iq = p & 63;
        float v[NHH];
        float mx = -1e30f;
#pragma unroll
        for (int h2 = 0; h2 < NHH; h2++) {
            v[h2] = __half2float(Ss[(h2 * 64 + kq) * 80 + iq]);
            mx = fmaxf(mx, v[h2]);
        }
        float sum = 0.f;
#pragma unroll
        for (int h2 = 0; h2 < NHH; h2++) {
            v[h2] = __expf(v[h2] - mx);
            sum += v[h2];
        }
        float inv = 1.f / sum;
#pragma unroll
        for (int h2 = 0; h2 < NHH; h2++)
            Ss[(h2 * 64 + kq) * 80 + iq] = __float2half_rn(v[h2] * inv);
    }
    __syncthreads();

    const int hh = tid >> 4, sub = tid & 15;
    const size_t base = ((size_t)(b * NHH + hh) * SS + kbq) * SS + ib;
#pragma unroll 1
    for (int m = 0; m < 32; m++) {
        int vid = m * 16 + sub;
        int kq = vid >> 3, ig = vid & 7;
        uint4 val = *(const uint4*)&Ss[(hh * 64 + kq) * 80 + ig * 8];
        *(uint4*)&g_attn[base + (size_t)kq * SS + ig * 8] = val;
    }
}

// ---------------------------------------------------------------------------
// AV GEMM per (b,h): Xt[b][16j+h][k] = sum_i attn[b,h,k,i] * Vh[b,h,i,j]
// 3-stage cp.async pipeline, CTA: 128 k x 64 j, i-chunks of 32.
// ---------------------------------------------------------------------------
__global__ void __launch_bounds__(256) av_gemm() {
    const int z = blockIdx.y;
    const int b_ = z >> 4, hn = z & 15;
    const int kb0 = blockIdx.x * 128;
    const __half* Aattn = g_attn + (size_t)z * SS * SS;
    const __half* V = g_Vh + (size_t)z * SS * DHH;

    __shared__ __half Asm[3][128][40];
    __shared__ __half Bsm[3][32][72];

    const int tid = threadIdx.x;
    const int w = tid >> 5, l = tid & 31;
    const int wm = w >> 1, wn = w & 1;

    const int ac0 = tid, ac1 = tid + 256;
    const int ar0 = ac0 >> 2, as0 = (ac0 & 3) * 8;
    const int ar1 = ac1 >> 2, as1 = (ac1 & 3) * 8;
    const int vr = tid >> 3, vs = (tid & 7) * 8;

    const int a_r = l & 15, a_c = (l >> 4) * 8;
    const int bt_r = (l & 7) + ((l >> 3) & 1) * 8;
    const int bt_c = ((l >> 4) & 1) * 8;

    const unsigned sA = sptr(&Asm[0][0][0]);
    const unsigned sB = sptr(&Bsm[0][0][0]);
    const unsigned Abs = 128 * 40 * 2, Bbs = 32 * 72 * 2;

    auto issue = [&](int it, int st) {
        const __half* Ag = Aattn + (size_t)kb0 * SS + it * 32;
        cpa16(sA + st * Abs + (unsigned)(ar0 * 40 + as0) * 2, Ag + (size_t)ar0 * SS + as0);
        cpa16(sA + st * Abs + (unsigned)(ar1 * 40 + as1) * 2, Ag + (size_t)ar1 * SS + as1);
        cpa16(sB + st * Bbs + (unsigned)(vr * 72 + vs) * 2, V + (size_t)(it * 32 + vr) * DHH + vs);
        cpa_commit();
    };

    float acc[2][4][4];
#pragma unroll
    for (int mt = 0; mt < 2; mt++)
#pragma unroll
        for (int nt = 0; nt < 4; nt++)
#pragma unroll
            for (int r = 0; r < 4; r++) acc[mt][nt][r] = 0.f;

    issue(0, 0);
    issue(1, 1);

    const int NIT = SS / 32;
    for (int it = 0; it < NIT; it++) {
        const int st = it % 3;
        if (it == NIT - 1) cpa_wait<0>(); else cpa_wait<1>();
        __syncthreads();
        if (it + 2 < NIT) issue(it + 2, (it + 2) % 3);

#pragma unroll
        for (int ks = 0; ks < 2; ks++) {
            unsigned a[2][4], bfr[2][4];
#pragma unroll
            for (int mt = 0; mt < 2; mt++) {
                int r = wm * 32 + mt * 16 + a_r;
                int c = ks * 16 + a_c;
                ldsm4(a[mt][0], a[mt][1], a[mt][2], a[mt][3],
                      sA + st * Abs + (unsigned)(r * 40 + c) * 2);
            }
#pragma unroll
            for (int np = 0; np < 2; np++) {
                int r = ks * 16 + bt_r;
                int c = wn * 32 + np * 16 + bt_c;
                ldsm4t(bfr[np][0], bfr[np][1], bfr[np][2], bfr[np][3],
                       sB + st * Bbs + (unsigned)(r * 72 + c) * 2);
            }
#pragma unroll
            for (int mt = 0; mt < 2; mt++)
#pragma unroll
                for (int nt = 0; nt < 4; nt++)
                    mma16816(acc[mt][nt], a[mt][0], a[mt][1], a[mt][2], a[mt][3],
                             bfr[nt >> 1][(nt & 1) * 2], bfr[nt >> 1][(nt & 1) * 2 + 1]);
        }
    }

    __half* Xb = g_Xt + (size_t)b_ * HH * SS;
#pragma unroll
    for (int mt = 0; mt < 2; mt++) {
        int m0 = kb0 + wm * 32 + mt * 16 + (l >> 2);
#pragma unroll
        for (int nt = 0; nt < 4; nt++) {
            int j0 = wn * 32 + nt * 8 + 2 * (l & 3);
            Xb[(size_t)(16 * j0 + hn) * SS + m0]           = __float2half_rn(acc[mt][nt][0]);
            Xb[(size_t)(16 * (j0 + 1) + hn) * SS + m0]     = __float2half_rn(acc[mt][nt][1]);
            Xb[(size_t)(16 * j0 + hn) * SS + m0 + 8]       = __float2half_rn(acc[mt][nt][2]);
            Xb[(size_t)(16 * (j0 + 1) + hn) * SS + m0 + 8] = __float2half_rn(acc[mt][nt][3]);
        }
    }
}

// ---------------------------------------------------------------------------
// Output projection: out = X @ Wo^T + bias (fp32 out). BM=64 BN=128 BK=32.
// A read from Xt via trans ldmatrix. Warp grid 2x4, warp tile 32x32.
// ---------------------------------------------------------------------------
__global__ void __launch_bounds__(256) outproj_gemm(const float* __restrict__ bias,
                                                    float* __restrict__ out) {
    const __half* Wo = g_W16[3];

    __shared__ __half At[2][32][72];    // [c 32][s 64]
    __shared__ __half Bt[2][128][40];

    const int tid = threadIdx.x;
    const int bm = blockIdx.y * 64, bn = blockIdx.x * 128;
    const int b_ = bm >> 11, sbase = bm & 2047;
    const int w = tid >> 5, l = tid & 31;
    const int wm = w >> 2, wn = w & 3;

    const int arow = tid >> 3, aseg = (tid & 7) * 8;     // 256 chunks (1/thread)
    const int brow = tid >> 1, bseg = (tid & 1) * 16;    // 2 uint4/thread

    const int at_r = (l & 7) + ((l >> 4) & 1) * 8;
    const int at_c = ((l >> 3) & 1) * 8;
    const int b_r = (l & 7) | ((l >> 1) & 8), b_c = l & 8;

    const unsigned sAt = sptr(&At[0][0][0]);
    const unsigned sBt = sptr(&Bt[0][0][0]);
    const unsigned Abs = 32 * 72 * 2, Bbs = 128 * 40 * 2;

    const __half* Ag = g_Xt + (size_t)b_ * HH * SS + (size_t)arow * SS + sbase + aseg;
    const __half* Bg = Wo + (size_t)(bn + brow) * HH + bseg;

    float acc[2][4][4];
#pragma unroll
    for (int mt = 0; mt < 2; mt++)
#pragma unroll
        for (int nt = 0; nt < 4; nt++)
#pragma unroll
            for (int r = 0; r < 4; r++) acc[mt][nt][r] = 0.f;

    uint4 va0 = *(const uint4*)Ag;
    uint4 vb0 = *(const uint4*)Bg;
    uint4 vb1 = *(const uint4*)(Bg + 8);
    *(uint4*)&At[0][arow][aseg] = va0;
    *(uint4*)&Bt[0][brow][bseg] = vb0; *(uint4*)&Bt[0][brow][bseg + 8] = vb1;
    __syncthreads();

    for (int kb = 0; kb < HH / 32; kb++) {
        const int buf = kb & 1;
        if (kb + 1 < HH / 32) {
            va0 = *(const uint4*)(Ag + (size_t)(kb + 1) * 32 * SS);
            const __half* Bn = Bg + (kb + 1) * 32;
            vb0 = *(const uint4*)Bn; vb1 = *(const uint4*)(Bn + 8);
        }
#pragma unroll
        for (int ks = 0; ks < 2; ks++) {
            unsigned a[2][4], bfr[2][4];
#pragma unroll
            for (int mt = 0; mt < 2; mt++) {
                int r = ks * 16 + at_r;
                int c = wm * 32 + mt * 16 + at_c;
                ldsm4t(a[mt][0], a[mt][1], a[mt][2], a[mt][3],
                       sAt + buf * Abs + (unsigned)(r * 72 + c) * 2);
            }
#pragma unroll
            for (int np = 0; np < 2; np++) {
                int r = wn * 32 + np * 16 + b_r;
                int c = ks * 16 + b_c;
                ldsm4(bfr[np][0], bfr[np][1], bfr[np][2], bfr[np][3],
                      sBt + buf * Bbs + (unsigned)(r * 40 + c) * 2);
            }
#pragma unroll
            for (int mt = 0; mt < 2; mt++)
#pragma unroll
                for (int nt = 0; nt < 4; nt++)
                    mma16816(acc[mt][nt], a[mt][0], a[mt][1], a[mt][2], a[mt][3],
                             bfr[nt >> 1][(nt & 1) * 2], bfr[nt >> 1][(nt & 1) * 2 + 1]);
        }
        if (kb + 1 < HH / 32) {
            const int nb = buf ^ 1;
            *(uint4*)&At[nb][arow][aseg] = va0;
            *(uint4*)&Bt[nb][brow][bseg] = vb0; *(uint4*)&Bt[nb][brow][bseg + 8] = vb1;
        }
        __syncthreads();
    }

#pragma unroll
    for (int nt = 0; nt < 4; nt++) {
        int c0 = bn + wn * 32 + nt * 8 + 2 * (l & 3);
        float bv0 = bias[c0], bv1 = bias[c0 + 1];
#pragma unroll
        for (int mt = 0; mt < 2; mt++) {
            int r0 = bm + wm * 32 + mt * 16 + (l >> 2);
            float2 v0 = make_float2(acc[mt][nt][0] + bv0, acc[mt][nt][1] + bv1);
            float2 v1 = make_float2(acc[mt][nt][2] + bv0, acc[mt][nt][3] + bv1);
            *(float2*)&out[(size_t)r0 * HH + c0] = v0;
            *(float2*)&out[(size_t)(r0 + 8) * HH + c0] = v1;
        }
    }
}

// ---------------------------------------------------------------------------
// Launch
// ---------------------------------------------------------------------------
extern "C" void kernel_launch(void* const* d_in, const int* in_sizes, int n_in,
                              void* d_out, int out_size)
{
    const float* KEY   = (const float*)d_in[0];
    const float* VALUE = (const float*)d_in[1];
    const float* QUERY = (const float*)d_in[2];
    const float* Wk_w  = (const float*)d_in[3];
    const float* Wk_b  = (const float*)d_in[4];
    const float* Wq_w  = (const float*)d_in[5];
    const float* Wq_b  = (const float*)d_in[6];
    const float* Wv_w  = (const float*)d_in[7];
    const float* Wv_b  = (const float*)d_in[8];
    const float* Wo_w  = (const float*)d_in[9];
    const float* Wo_b  = (const float*)d_in[10];
    float* out = (float*)d_out;

    static bool attr_done = false;
    if (!attr_done) {
        cudaFuncSetAttribute(score_softmax, cudaFuncAttributeMaxDynamicSharedMemorySize, 210000);
        attr_done = true;
    }

    const int total4 = 3 * IN4 + 4 * W4;
    cvt_all<<<total4 / 256, 256>>>((const float4*)KEY, (const float4*)QUERY,
                                   (const float4*)VALUE, (const float4*)Wk_w,
                                   (const float4*)Wq_w, (const float4*)Wv_w,
                                   (const float4*)Wo_w);

    dim3 pg(HH / 128, (BB * SS) / 128, 3);         // (8, 32, 3) = 768 CTAs
    proj_fused<<<pg, 256>>>(Wk_b, Wq_b, Wv_b);

    const int smbytes = (4 * 64 * 72 + 16 * 64 * 80) * 2;   // 200,704
    dim3 sg(SS / 64, SS / 64, BB);                 // (32, 32, 2)
    score_softmax<<<sg, 256, smbytes>>>();

    dim3 ag(SS / 128, BB * NHH);                   // (16, 32)
    av_gemm<<<ag, 256>>>();

    dim3 og(HH / 128, (BB * SS) / 64);             // (8, 64) = 512 CTAs
    outproj_gemm<<<og, 256>>>(Wo_b, out);
}

// round 7
// speedup vs baseline: 4.9566x; 1.0390x over previous
#include <cuda_runtime.h>
#include <cuda_fp16.h>

#define BB  2
#define SS  2048
#define DD  1024
#define HH  1024
#define NHH 16
#define DHH 64

// ---------------------------------------------------------------------------
// Static scratch
// ---------------------------------------------------------------------------
__device__ __half g_A16[3][BB * SS * DD];          // fp16 KEY, QUERY, VALUE
__device__ __half g_W16[4][HH * DD];               // fp16 Wk, Wq, Wv, Wo
__device__ __half g_Kh[BB * NHH * SS * DHH];       // head-split projections
__device__ __half g_Qh[BB * NHH * SS * DHH];
__device__ __half g_Vh[BB * NHH * SS * DHH];
__device__ __half g_attn[(size_t)BB * NHH * SS * SS];   // attn [b,h,k,i]
__device__ __half g_Xt[BB * HH * SS];              // X transposed [b][c][s]

// ---------------------------------------------------------------------------
// PTX helpers
// ---------------------------------------------------------------------------
__device__ __forceinline__ unsigned sptr(const void* p) {
    unsigned a;
    asm("{.reg .u64 t; cvta.to.shared.u64 t, %1; cvt.u32.u64 %0, t;}" : "=r"(a) : "l"(p));
    return a;
}
__device__ __forceinline__ void ldsm4(unsigned& r0, unsigned& r1, unsigned& r2, unsigned& r3, unsigned a) {
    asm volatile("ldmatrix.sync.aligned.m8n8.x4.shared.b16 {%0,%1,%2,%3},[%4];\n"
                 : "=r"(r0), "=r"(r1), "=r"(r2), "=r"(r3) : "r"(a));
}
__device__ __forceinline__ void ldsm4t(unsigned& r0, unsigned& r1, unsigned& r2, unsigned& r3, unsigned a) {
    asm volatile("ldmatrix.sync.aligned.m8n8.x4.trans.shared.b16 {%0,%1,%2,%3},[%4];\n"
                 : "=r"(r0), "=r"(r1), "=r"(r2), "=r"(r3) : "r"(a));
}
__device__ __forceinline__ void mma16816(float* c, unsigned a0, unsigned a1, unsigned a2, unsigned a3,
                                         unsigned b0, unsigned b1) {
    asm volatile("mma.sync.aligned.m16n8k16.row.col.f32.f16.f16.f32 "
                 "{%0,%1,%2,%3},{%4,%5,%6,%7},{%8,%9},{%0,%1,%2,%3};\n"
                 : "+f"(c[0]), "+f"(c[1]), "+f"(c[2]), "+f"(c[3])
                 : "r"(a0), "r"(a1), "r"(a2), "r"(a3), "r"(b0), "r"(b1));
}
__device__ __forceinline__ void cpa16(unsigned d, const void* s) {
    asm volatile("cp.async.cg.shared.global [%0],[%1],16;\n" :: "r"(d), "l"(s));
}
__device__ __forceinline__ void cpa_commit() { asm volatile("cp.async.commit_group;\n"); }
template <int N> __device__ __forceinline__ void cpa_wait() {
    asm volatile("cp.async.wait_group %0;\n" :: "n"(N));
}

// ---------------------------------------------------------------------------
// Fused fp32->fp16 conversion, 2 float4 per thread.
// ---------------------------------------------------------------------------
#define IN4 (BB * SS * DD / 4)
#define W4  (HH * DD / 4)
#define TOT4 (3 * IN4 + 4 * W4)
__global__ void __launch_bounds__(256) cvt_all(const float4* __restrict__ k,
                                               const float4* __restrict__ q,
                                               const float4* __restrict__ v,
                                               const float4* __restrict__ wk,
                                               const float4* __restrict__ wq,
                                               const float4* __restrict__ wv,
                                               const float4* __restrict__ wo)
{
#pragma unroll
    for (int e = 0; e < 2; e++) {
        int idx = (blockIdx.x * 2 + e) * 256 + threadIdx.x;
        const float4* src;
        __half2* dst;
        int li;
        if (idx < 3 * IN4) {
            int which = idx / IN4;
            li = idx - which * IN4;
            src = (which == 0) ? k : (which == 1) ? q : v;
            dst = (__half2*)g_A16[which];
        } else {
            int r = idx - 3 * IN4;
            int which = r / W4;
            li = r - which * W4;
            src = (which == 0) ? wk : (which == 1) ? wq : (which == 2) ? wv : wo;
            dst = (__half2*)g_W16[which];
        }
        float4 val = src[li];
        dst[li * 2]     = __floats2half2_rn(val.x, val.y);
        dst[li * 2 + 1] = __floats2half2_rn(val.z, val.w);
    }
}

// ---------------------------------------------------------------------------
// Fused projection GEMM (K, Q, V in one launch; which = blockIdx.z).
// BM=128 BN=128 BK=32, 3-stage cp.async.
// ---------------------------------------------------------------------------
__global__ void __launch_bounds__(256) proj_fused(const float* __restrict__ bk,
                                                  const float* __restrict__ bq,
                                                  const float* __restrict__ bv) {
    const int which = blockIdx.z;
    const __half* A = g_A16[which];
    const __half* W = g_W16[which];
    __half* out = (which == 0) ? g_Kh : (which == 1) ? g_Qh : g_Vh;
    const float* bias = (which == 0) ? bk : (which == 1) ? bq : bv;

    __shared__ union {
        __half t[3][2][128][40];
        __half C[128][136];
    } sh;

    const int tid = threadIdx.x;
    const int bm = blockIdx.y * 128, bn = blockIdx.x * 128;
    const int w = tid >> 5, l = tid & 31;
    const int wm = w >> 2, wn = w & 3;

    const int c0 = tid, c1 = tid + 256;
    const int ar0 = c0 >> 2, as0 = (c0 & 3) * 8;
    const int ar1 = c1 >> 2, as1 = (c1 & 3) * 8;

    const unsigned sBase = sptr(&sh.t[0][0][0][0]);
    const unsigned stgStride = 2 * 128 * 40 * 2;
    const unsigned bOff = 128 * 40 * 2;

    auto issue = [&](int kb, int st) {
        const __half* Ag = A + (size_t)bm * DD + kb * 32;
        const __half* Bg = W + (size_t)bn * DD + kb * 32;
        unsigned s = sBase + st * stgStride;
        cpa16(s + (unsigned)(ar0 * 40 + as0) * 2, Ag + (size_t)ar0 * DD + as0);
        cpa16(s + (unsigned)(ar1 * 40 + as1) * 2, Ag + (size_t)ar1 * DD + as1);
        cpa16(s + bOff + (unsigned)(ar0 * 40 + as0) * 2, Bg + (size_t)ar0 * DD + as0);
        cpa16(s + bOff + (unsigned)(ar1 * 40 + as1) * 2, Bg + (size_t)ar1 * DD + as1);
        cpa_commit();
    };

    float acc[4][4][4];
#pragma unroll
    for (int mt = 0; mt < 4; mt++)
#pragma unroll
        for (int nt = 0; nt < 4; nt++)
#pragma unroll
            for (int r = 0; r < 4; r++) acc[mt][nt][r] = 0.f;

    const int a_r = l & 15, a_c = (l >> 4) * 8;
    const int b_r = (l & 7) | ((l >> 1) & 8), b_c = l & 8;

    issue(0, 0);
    issue(1, 1);

    const int NKB = DD / 32;
    for (int kb = 0; kb < NKB; kb++) {
        const int st = kb % 3;
        if (kb == NKB - 1) cpa_wait<0>(); else cpa_wait<1>();
        __syncthreads();
        if (kb + 2 < NKB) issue(kb + 2, (kb + 2) % 3);

        const unsigned sA = sBase + st * stgStride;
        const unsigned sB = sA + bOff;
#pragma unroll
        for (int ks = 0; ks < 2; ks++) {
            unsigned a[4][4], bfr[2][4];
#pragma unroll
            for (int mt = 0; mt < 4; mt++) {
                int r = wm * 64 + mt * 16 + a_r;
                int c = ks * 16 + a_c;
                ldsm4(a[mt][0], a[mt][1], a[mt][2], a[mt][3],
                      sA + (unsigned)(r * 40 + c) * 2);
            }
#pragma unroll
            for (int np = 0; np < 2; np++) {
                int r = wn * 32 + np * 16 + b_r;
                int c = ks * 16 + b_c;
                ldsm4(bfr[np][0], bfr[np][1], bfr[np][2], bfr[np][3],
                      sB + (unsigned)(r * 40 + c) * 2);
            }
#pragma unroll
            for (int mt = 0; mt < 4; mt++)
#pragma unroll
                for (int nt = 0; nt < 4; nt++)
                    mma16816(acc[mt][nt], a[mt][0], a[mt][1], a[mt][2], a[mt][3],
                             bfr[nt >> 1][(nt & 1) * 2], bfr[nt >> 1][(nt & 1) * 2 + 1]);
        }
    }
    __syncthreads();

#pragma unroll
    for (int nt = 0; nt < 4; nt++) {
        int c0v = wn * 32 + nt * 8 + 2 * (l & 3);
        float bv0 = bias[bn + c0v], bv1 = bias[bn + c0v + 1];
#pragma unroll
        for (int mt = 0; mt < 4; mt++) {
            int r0 = wm * 64 + mt * 16 + (l >> 2);
            *(__half2*)&sh.C[r0][c0v]     = __floats2half2_rn(acc[mt][nt][0] + bv0, acc[mt][nt][1] + bv1);
            *(__half2*)&sh.C[r0 + 8][c0v] = __floats2half2_rn(acc[mt][nt][2] + bv0, acc[mt][nt][3] + bv1);
        }
    }
    __syncthreads();

    const int h = tid & 15, sg = tid >> 4;
#pragma unroll
    for (int sl = 0; sl < 8; sl++) {
        int s = sg * 8 + sl;
        int m = bm + s;
        int b_ = m >> 11, sloc = m & 2047;
        __half tmp[8];
#pragma unroll
        for (int dd = 0; dd < 8; dd++) tmp[dd] = sh.C[s][h + 16 * dd];
        *(uint4*)&out[(((size_t)(b_ * NHH + h)) * SS + sloc) * DHH + (bn >> 4)] = *(uint4*)tmp;
    }
}

// ---------------------------------------------------------------------------
// Fused score + head-softmax v3. CTA: (b, 64 i keys, 32 k queries), 16 heads.
// 2 CTAs/SM (101 KB smem). One sync per head-iter (2-buffer proof: at iter-h's
// sync all threads completed body h-1, so buffer (h+1)%2 is free).
// smem: Q[2][32][72], K[2][64][72], Ss[16][32][72].
// ---------------------------------------------------------------------------
__global__ void __launch_bounds__(256, 2) score_softmax() {
    extern __shared__ __half smbuf[];
    __half* Qs = smbuf;                         // 2*32*72
    __half* Ks = smbuf + 2 * 32 * 72;           // 2*64*72
    __half* Ss = smbuf + 2 * 32 * 72 + 2 * 64 * 72;   // 16*32*72

    const int b = blockIdx.z;
    const int ib = blockIdx.x * 64;     // i (key) base
    const int kbq = blockIdx.y * 32;    // k (query) base
    const int tid = threadIdx.x;
    const int w = tid >> 5, l = tid & 31;
    const int wm = w >> 2, wn = w & 3;  // wm: k-half (2x16), wn: i-quarter (4x16)

    const unsigned sQ = sptr(Qs);
    const unsigned sK = sptr(Ks);
    const unsigned bufQ = 32 * 72 * 2;
    const unsigned bufK = 64 * 72 * 2;

    // loaders: K = 512 chunks (2/thread), Q = 256 chunks (1/thread)
    const int kr0 = tid >> 3, ks0 = (tid & 7) * 8;
    const int kc1 = tid + 256;
    const int kr1 = kc1 >> 3, ks1 = (kc1 & 7) * 8;
    const int qr = tid >> 3, qs = (tid & 7) * 8;

    const int a_r = l & 15, a_c = (l >> 4) * 8;
    const int b_r = (l & 7) | ((l >> 1) & 8), b_c = l & 8;

    auto issue = [&](int h, int bf) {
        const __half* Qg = g_Qh + (((size_t)(b * NHH + h)) * SS + kbq) * DHH;
        const __half* Kg = g_Kh + (((size_t)(b * NHH + h)) * SS + ib) * DHH;
        cpa16(sQ + bf * bufQ + (unsigned)(qr * 72 + qs) * 2, Qg + qr * DHH + qs);
        cpa16(sK + bf * bufK + (unsigned)(kr0 * 72 + ks0) * 2, Kg + kr0 * DHH + ks0);
        cpa16(sK + bf * bufK + (unsigned)(kr1 * 72 + ks1) * 2, Kg + kr1 * DHH + ks1);
        cpa_commit();
    };

    issue(0, 0);

    for (int h = 0; h < NHH; h++) {
        const int bf = h & 1;
        cpa_wait<0>();
        __syncthreads();
        if (h + 1 < NHH) issue(h + 1, bf ^ 1);

        float acc[2][4];
#pragma unroll
        for (int nt = 0; nt < 2; nt++)
#pragma unroll
            for (int r = 0; r < 4; r++) acc[nt][r] = 0.f;

#pragma unroll
        for (int ks = 0; ks < 4; ks++) {
            unsigned a[4], bf4[4];
            {
                int r = wm * 16 + a_r;
                int c = ks * 16 + a_c;
                ldsm4(a[0], a[1], a[2], a[3],
                      sQ + bf * bufQ + (unsigned)(r * 72 + c) * 2);
            }
            {
                int r = wn * 16 + b_r;
                int c = ks * 16 + b_c;
                ldsm4(bf4[0], bf4[1], bf4[2], bf4[3],
                      sK + bf * bufK + (unsigned)(r * 72 + c) * 2);
            }
#pragma unroll
            for (int nt = 0; nt < 2; nt++)
                mma16816(acc[nt], a[0], a[1], a[2], a[3], bf4[nt * 2], bf4[nt * 2 + 1]);
        }

        // store scaled scores: Ss[h][k 32][i 72-pad]
#pragma unroll
        for (int nt = 0; nt < 2; nt++) {
            int r = wm * 16 + (l >> 2);              // k
            int c = wn * 16 + nt * 8 + 2 * (l & 3);  // i
            *(__half2*)&Ss[(h * 32 + r) * 72 + c] =
                __floats2half2_rn(acc[nt][0] * 0.125f, acc[nt][1] * 0.125f);
            *(__half2*)&Ss[(h * 32 + r + 8) * 72 + c] =
                __floats2half2_rn(acc[nt][2] * 0.125f, acc[nt][3] * 0.125f);
        }
    }
    __syncthreads();

    // softmax over heads at each (k,i); 32k*64i = 2048 points, 8 iters
#pragma unroll 1
    for (int it = 0; it < 8; it++) {
        int p = it * 256 + tid;
        int kq = p >> 6, iq = p & 63;
        float v[NHH];
        float mx = -1e30f;
#pragma unroll
        for (int h2 = 0; h2 < NHH; h2++) {
            v[h2] = __half2float(Ss[(h2 * 32 + kq) * 72 + iq]);
            mx = fmaxf(mx, v[h2]);
        }
        float sum = 0.f;
#pragma unroll
        for (int h2 = 0; h2 < NHH; h2++) {
            v[h2] = __expf(v[h2] - mx);
            sum += v[h2];
        }
        float inv = 1.f / sum;
#pragma unroll
        for (int h2 = 0; h2 < NHH; h2++)
            Ss[(h2 * 32 + kq) * 72 + iq] = __float2half_rn(v[h2] * inv);
    }
    __syncthreads();

    // coalesced uint4 writeout: attn[b,h,k,i]
    const int hh = tid >> 4, sub = tid & 15;
    const size_t base = ((size_t)(b * NHH + hh) * SS + kbq) * SS + ib;
#pragma unroll 1
    for (int m = 0; m < 16; m++) {
        int vid = m * 16 + sub;            // 256 vecs per head: k*8 + ig
        int kq = vid >> 3, ig = vid & 7;
        uint4 val = *(const uint4*)&Ss[(hh * 32 + kq) * 72 + ig * 8];
        *(uint4*)&g_attn[base + (size_t)kq * SS + ig * 8] = val;
    }
}

// ---------------------------------------------------------------------------
// AV GEMM per (b,h): Xt[b][16j+h][k] = sum_i attn[b,h,k,i] * Vh[b,h,i,j]
// 4-stage cp.async pipeline, CTA: 128 k x 64 j, i-chunks of 32.
// ---------------------------------------------------------------------------
__global__ void __launch_bounds__(256) av_gemm() {
    const int z = blockIdx.y;
    const int b_ = z >> 4, hn = z & 15;
    const int kb0 = blockIdx.x * 128;
    const __half* Aattn = g_attn + (size_t)z * SS * SS;
    const __half* V = g_Vh + (size_t)z * SS * DHH;

    __shared__ __half Asm[4][128][40];
    __shared__ __half Bsm[4][32][72];

    const int tid = threadIdx.x;
    const int w = tid >> 5, l = tid & 31;
    const int wm = w >> 1, wn = w & 1;

    const int ac0 = tid, ac1 = tid + 256;
    const int ar0 = ac0 >> 2, as0 = (ac0 & 3) * 8;
    const int ar1 = ac1 >> 2, as1 = (ac1 & 3) * 8;
    const int vr = tid >> 3, vs = (tid & 7) * 8;

    const int a_r = l & 15, a_c = (l >> 4) * 8;
    const int bt_r = (l & 7) + ((l >> 3) & 1) * 8;
    const int bt_c = ((l >> 4) & 1) * 8;

    const unsigned sA = sptr(&Asm[0][0][0]);
    const unsigned sB = sptr(&Bsm[0][0][0]);
    const unsigned Abs = 128 * 40 * 2, Bbs = 32 * 72 * 2;

    auto issue = [&](int it, int st) {
        const __half* Ag = Aattn + (size_t)kb0 * SS + it * 32;
        cpa16(sA + st * Abs + (unsigned)(ar0 * 40 + as0) * 2, Ag + (size_t)ar0 * SS + as0);
        cpa16(sA + st * Abs + (unsigned)(ar1 * 40 + as1) * 2, Ag + (size_t)ar1 * SS + as1);
        cpa16(sB + st * Bbs + (unsigned)(vr * 72 + vs) * 2, V + (size_t)(it * 32 + vr) * DHH + vs);
        cpa_commit();
    };

    float acc[2][4][4];
#pragma unroll
    for (int mt = 0; mt < 2; mt++)
#pragma unroll
        for (int nt = 0; nt < 4; nt++)
#pragma unroll
            for (int r = 0; r < 4; r++) acc[mt][nt][r] = 0.f;

    issue(0, 0);
    issue(1, 1);
    issue(2, 2);

    const int NIT = SS / 32;
    for (int it = 0; it < NIT; it++) {
        const int st = it & 3;
        // wait so that group `it` is complete, tail-exact
        int rem = NIT - 1 - it;
        if (rem >= 2) cpa_wait<2>();
        else if (rem == 1) cpa_wait<1>();
        else cpa_wait<0>();
        __syncthreads();
        if (it + 3 < NIT) issue(it + 3, (it + 3) & 3);

#pragma unroll
        for (int ks = 0; ks < 2; ks++) {
            unsigned a[2][4], bfr[2][4];
#pragma unroll
            for (int mt = 0; mt < 2; mt++) {
                int r = wm * 32 + mt * 16 + a_r;
                int c = ks * 16 + a_c;
                ldsm4(a[mt][0], a[mt][1], a[mt][2], a[mt][3],
                      sA + st * Abs + (unsigned)(r * 40 + c) * 2);
            }
#pragma unroll
            for (int np = 0; np < 2; np++) {
                int r = ks * 16 + bt_r;
                int c = wn * 32 + np * 16 + bt_c;
                ldsm4t(bfr[np][0], bfr[np][1], bfr[np][2], bfr[np][3],
                       sB + st * Bbs + (unsigned)(r * 72 + c) * 2);
            }
#pragma unroll
            for (int mt = 0; mt < 2; mt++)
#pragma unroll
                for (int nt = 0; nt < 4; nt++)
                    mma16816(acc[mt][nt], a[mt][0], a[mt][1], a[mt][2], a[mt][3],
                             bfr[nt >> 1][(nt & 1) * 2], bfr[nt >> 1][(nt & 1) * 2 + 1]);
        }
    }

    __half* Xb = g_Xt + (size_t)b_ * HH * SS;
#pragma unroll
    for (int mt = 0; mt < 2; mt++) {
        int m0 = kb0 + wm * 32 + mt * 16 + (l >> 2);
#pragma unroll
        for (int nt = 0; nt < 4; nt++) {
            int j0 = wn * 32 + nt * 8 + 2 * (l & 3);
            Xb[(size_t)(16 * j0 + hn) * SS + m0]           = __float2half_rn(acc[mt][nt][0]);
            Xb[(size_t)(16 * (j0 + 1) + hn) * SS + m0]     = __float2half_rn(acc[mt][nt][1]);
            Xb[(size_t)(16 * j0 + hn) * SS + m0 + 8]       = __float2half_rn(acc[mt][nt][2]);
            Xb[(size_t)(16 * (j0 + 1) + hn) * SS + m0 + 8] = __float2half_rn(acc[mt][nt][3]);
        }
    }
}

// ---------------------------------------------------------------------------
// Output projection: out = X @ Wo^T + bias (fp32 out). BM=64 BN=128 BK=32.
// ---------------------------------------------------------------------------
__global__ void __launch_bounds__(256) outproj_gemm(const float* __restrict__ bias,
                                                    float* __restrict__ out) {
    const __half* Wo = g_W16[3];

    __shared__ __half At[2][32][72];
    __shared__ __half Bt[2][128][40];

    const int tid = threadIdx.x;
    const int bm = blockIdx.y * 64, bn = blockIdx.x * 128;
    const int b_ = bm >> 11, sbase = bm & 2047;
    const int w = tid >> 5, l = tid & 31;
    const int wm = w >> 2, wn = w & 3;

    const int arow = tid >> 3, aseg = (tid & 7) * 8;
    const int brow = tid >> 1, bseg = (tid & 1) * 16;

    const int at_r = (l & 7) + ((l >> 4) & 1) * 8;
    const int at_c = ((l >> 3) & 1) * 8;
    const int b_r = (l & 7) | ((l >> 1) & 8), b_c = l & 8;

    const unsigned sAt = sptr(&At[0][0][0]);
    const unsigned sBt = sptr(&Bt[0][0][0]);
    const unsigned Abs = 32 * 72 * 2, Bbs = 128 * 40 * 2;

    const __half* Ag = g_Xt + (size_t)b_ * HH * SS + (size_t)arow * SS + sbase + aseg;
    const __half* Bg = Wo + (size_t)(bn + brow) * HH + bseg;

    float acc[2][4][4];
#pragma unroll
    for (int mt = 0; mt < 2; mt++)
#pragma unroll
        for (int nt = 0; nt < 4; nt++)
#pragma unroll
            for (int r = 0; r < 4; r++) acc[mt][nt][r] = 0.f;

    uint4 va0 = *(const uint4*)Ag;
    uint4 vb0 = *(const uint4*)Bg;
    uint4 vb1 = *(const uint4*)(Bg + 8);
    *(uint4*)&At[0][arow][aseg] = va0;
    *(uint4*)&Bt[0][brow][bseg] = vb0; *(uint4*)&Bt[0][brow][bseg + 8] = vb1;
    __syncthreads();

    for (int kb = 0; kb < HH / 32; kb++) {
        const int buf = kb & 1;
        if (kb + 1 < HH / 32) {
            va0 = *(const uint4*)(Ag + (size_t)(kb + 1) * 32 * SS);
            const __half* Bn = Bg + (kb + 1) * 32;
            vb0 = *(const uint4*)Bn; vb1 = *(const uint4*)(Bn + 8);
        }
#pragma unroll
        for (int ks = 0; ks < 2; ks++) {
            unsigned a[2][4], bfr[2][4];
#pragma unroll
            for (int mt = 0; mt < 2; mt++) {
                int r = ks * 16 + at_r;
                int c = wm * 32 + mt * 16 + at_c;
                ldsm4t(a[mt][0], a[mt][1], a[mt][2], a[mt][3],
                       sAt + buf * Abs + (unsigned)(r * 72 + c) * 2);
            }
#pragma unroll
            for (int np = 0; np < 2; np++) {
                int r = wn * 32 + np * 16 + b_r;
                int c = ks * 16 + b_c;
                ldsm4(bfr[np][0], bfr[np][1], bfr[np][2], bfr[np][3],
                      sBt + buf * Bbs + (unsigned)(r * 40 + c) * 2);
            }
#pragma unroll
            for (int mt = 0; mt < 2; mt++)
#pragma unroll
                for (int nt = 0; nt < 4; nt++)
                    mma16816(acc[mt][nt], a[mt][0], a[mt][1], a[mt][2], a[mt][3],
                             bfr[nt >> 1][(nt & 1) * 2], bfr[nt >> 1][(nt & 1) * 2 + 1]);
        }
        if (kb + 1 < HH / 32) {
            const int nb = buf ^ 1;
            *(uint4*)&At[nb][arow][aseg] = va0;
            *(uint4*)&Bt[nb][brow][bseg] = vb0; *(uint4*)&Bt[nb][brow][bseg + 8] = vb1;
        }
        __syncthreads();
    }

#pragma unroll
    for (int nt = 0; nt < 4; nt++) {
        int c0 = bn + wn * 32 + nt * 8 + 2 * (l & 3);
        float bv0 = bias[c0], bv1 = bias[c0 + 1];
#pragma unroll
        for (int mt = 0; mt < 2; mt++) {
            int r0 = bm + wm * 32 + mt * 16 + (l >> 2);
            float2 v0 = make_float2(acc[mt][nt][0] + bv0, acc[mt][nt][1] + bv1);
            float2 v1 = make_float2(acc[mt][nt][2] + bv0, acc[mt][nt][3] + bv1);
            *(float2*)&out[(size_t)r0 * HH + c0] = v0;
            *(float2*)&out[(size_t)(r0 + 8) * HH + c0] = v1;
        }
    }
}

// ---------------------------------------------------------------------------
// Launch
// ---------------------------------------------------------------------------
extern "C" void kernel_launch(void* const* d_in, const int* in_sizes, int n_in,
                              void* d_out, int out_size)
{
    const float* KEY   = (const float*)d_in[0];
    const float* VALUE = (const float*)d_in[1];
    const float* QUERY = (const float*)d_in[2];
    const float* Wk_w  = (const float*)d_in[3];
    const float* Wk_b  = (const float*)d_in[4];
    const float* Wq_w  = (const float*)d_in[5];
    const float* Wq_b  = (const float*)d_in[6];
    const float* Wv_w  = (const float*)d_in[7];
    const float* Wv_b  = (const float*)d_in[8];
    const float* Wo_w  = (const float*)d_in[9];
    const float* Wo_b  = (const float*)d_in[10];
    float* out = (float*)d_out;

    const int smbytes = (2 * 32 * 72 + 2 * 64 * 72 + 16 * 32 * 72) * 2;   // 101,376
    static bool attr_done = false;
    if (!attr_done) {
        cudaFuncSetAttribute(score_softmax, cudaFuncAttributeMaxDynamicSharedMemorySize, smbytes);
        attr_done = true;
    }

    cvt_all<<<TOT4 / 512, 256>>>((const float4*)KEY, (const float4*)QUERY,
                                 (const float4*)VALUE, (const float4*)Wk_w,
                                 (const float4*)Wq_w, (const float4*)Wv_w,
                                 (const float4*)Wo_w);

    dim3 pg(HH / 128, (BB * SS) / 128, 3);         // 768 CTAs
    proj_fused<<<pg, 256>>>(Wk_b, Wq_b, Wv_b);

    dim3 sg(SS / 64, SS / 32, BB);                 // (32, 64, 2) = 4096 CTAs
    score_softmax<<<sg, 256, smbytes>>>();

    dim3 ag(SS / 128, BB * NHH);                   // (16, 32)
    av_gemm<<<ag, 256>>>();

    dim3 og(HH / 128, (BB * SS) / 64);             // (8, 64)
    outproj_gemm<<<og, 256>>>(Wo_b, out);
}